// round 12
// baseline (speedup 1.0000x reference)
#include <cuda_runtime.h>
#include <cuda_bf16.h>
#include <math.h>
#include <stdint.h>

// Problem constants
#define B_   8
#define T_   2048
#define C_   1024
#define H_   64
#define NROW (B_ * T_)          // 16384

// Scratch: Q (pre-scaled 1/32) and K as single bf16; V as bf16 hi/lo.
__device__ __nv_bfloat16 g_Qh[NROW * H_];
__device__ __nv_bfloat16 g_Kh[NROW * H_];
__device__ __nv_bfloat16 g_Vh[NROW * H_], g_Vl[NROW * H_];
__device__ __nv_bfloat16 g_Wh[3 * H_ * C_];
__device__ __nv_bfloat16 g_Wl[3 * H_ * C_];

__device__ __forceinline__ uint32_t smem_u32(const void* p) {
    uint32_t a;
    asm("{ .reg .u64 t; cvta.to.shared.u64 t, %1; cvt.u32.u64 %0, t; }" : "=r"(a) : "l"(p));
    return a;
}
__device__ __forceinline__ void ldsm4(uint32_t& r0, uint32_t& r1, uint32_t& r2,
                                      uint32_t& r3, uint32_t addr) {
    asm volatile("ldmatrix.sync.aligned.m8n8.x4.shared.b16 {%0,%1,%2,%3}, [%4];"
                 : "=r"(r0), "=r"(r1), "=r"(r2), "=r"(r3) : "r"(addr));
}
__device__ __forceinline__ void ldsm4t(uint32_t& r0, uint32_t& r1, uint32_t& r2,
                                       uint32_t& r3, uint32_t addr) {
    asm volatile("ldmatrix.sync.aligned.m8n8.x4.trans.shared.b16 {%0,%1,%2,%3}, [%4];"
                 : "=r"(r0), "=r"(r1), "=r"(r2), "=r"(r3) : "r"(addr));
}
__device__ __forceinline__ void mma16816(float* d, uint32_t a0, uint32_t a1,
                                         uint32_t a2, uint32_t a3,
                                         uint32_t b0, uint32_t b1) {
    asm volatile("mma.sync.aligned.m16n8k16.row.col.f32.bf16.bf16.f32 "
                 "{%0,%1,%2,%3}, {%4,%5,%6,%7}, {%8,%9}, {%0,%1,%2,%3};"
                 : "+f"(d[0]), "+f"(d[1]), "+f"(d[2]), "+f"(d[3])
                 : "r"(a0), "r"(a1), "r"(a2), "r"(a3), "r"(b0), "r"(b1));
}
__device__ __forceinline__ uint32_t pk2(float lo, float hi) {
    uint32_t r;
    asm("cvt.rn.bf16x2.f32 %0, %1, %2;" : "=r"(r) : "f"(hi), "f"(lo));
    return r;
}
__device__ __forceinline__ float bfround(float v) {
    return __bfloat162float(__float2bfloat16(v));
}
__device__ __forceinline__ uint32_t pack_bf16(__nv_bfloat16 a, __nv_bfloat16 b) {
    __nv_bfloat162 t; t.x = a; t.y = b;
    return *(uint32_t*)&t;
}
#define CP16(dst, src) \
    asm volatile("cp.async.cg.shared.global [%0], [%1], 16;" :: "r"(dst), "l"(src) : "memory")
#define CP_COMMIT() asm volatile("cp.async.commit_group;" ::: "memory")

// ---------------------------------------------------------------------------
// Prep: split weights fp32 -> bf16 hi/lo, transpose [k][n] -> [mat][n][k]
// ---------------------------------------------------------------------------
__global__ void prep_w(const float* __restrict__ wq,
                       const float* __restrict__ wk,
                       const float* __restrict__ wv)
{
    int e = blockIdx.x * 256 + threadIdx.x;
    if (e >= 3 * H_ * C_) return;
    int mat = e / (H_ * C_);
    int r   = e % (H_ * C_);
    int n   = r / C_;
    int k   = r % C_;
    const float* w = (mat == 0) ? wq : (mat == 1) ? wk : wv;
    float v = w[k * H_ + n];
    __nv_bfloat16 h = __float2bfloat16(v);
    g_Wh[e] = h;
    g_Wl[e] = __float2bfloat16(v - __bfloat162float(h));
}

// ---------------------------------------------------------------------------
// Projection via mma.sync, software-pipelined.
//   Q/K: single-bf16 MMA (xh.wh). V: 3-way hi/lo split (accuracy-critical).
//   W: cp.async double buffer (Wl staged for V only); x: reg prefetch ->
//   single-buffered bf16 hi/lo smem. grid = 128 CTAs x 256 threads.
// ---------------------------------------------------------------------------
#define KP 72
#define XBUF_B 36864                           // xh(18432) + xl(18432)
#define WBUF_B 36864                           // Wh 3 mats (27648) + Wl V (9216)
#define WB(b)  (XBUF_B + (b) * WBUF_B)
#define PROJ_SMEM (XBUF_B + 2 * WBUF_B)        // 110592

__global__ __launch_bounds__(256) void proj_mma(
    const float* __restrict__ x,
    const float* __restrict__ bq,
    const float* __restrict__ bk,
    const float* __restrict__ bv)
{
    extern __shared__ char smc[];
    const uint32_t sb = smem_u32(smc);
    const int tid  = threadIdx.x;
    const int wid  = tid >> 5;
    const int lane = tid & 31;
    const int m0   = blockIdx.x * 128;

    float acc[3][8][4];
    #pragma unroll
    for (int m = 0; m < 3; ++m)
        #pragma unroll
        for (int n = 0; n < 8; ++n)
            #pragma unroll
            for (int i = 0; i < 4; ++i) acc[m][n][i] = 0.f;

    const int a_row  = lane & 15;
    const int a_half = lane >> 4;
    const uint32_t a_off = ((wid * 16 + a_row) * KP + a_half * 8) * 2;
    const int l8   = lane & 7;
    const int bgrp = lane >> 3;
    const int b_n  = ((bgrp & 2) ? 8 : 0) + l8;
    const int b_h  = bgrp & 1;
    const uint32_t b_off = (b_n * KP + b_h * 8) * 2;

    float4 X[8];
    auto ldg_x = [&](int kc) {
        #pragma unroll
        for (int it = 0; it < 8; ++it) {
            int u  = tid + it * 256;
            int r  = u >> 4;
            int c4 = (u & 15) << 2;
            X[it] = *(const float4*)(x + (size_t)(m0 + r) * C_ + kc + c4);
        }
    };
    auto cvt_x = [&]() {
        #pragma unroll
        for (int it = 0; it < 8; ++it) {
            int u  = tid + it * 256;
            int r  = u >> 4;
            int c4 = (u & 15) << 2;
            float4 t = X[it];
            __nv_bfloat16 h0 = __float2bfloat16(t.x);
            __nv_bfloat16 h1 = __float2bfloat16(t.y);
            __nv_bfloat16 h2 = __float2bfloat16(t.z);
            __nv_bfloat16 h3 = __float2bfloat16(t.w);
            uint2 hh = make_uint2(pack_bf16(h0, h1), pack_bf16(h2, h3));
            uint2 ll = make_uint2(
                pack_bf16(__float2bfloat16(t.x - __bfloat162float(h0)),
                          __float2bfloat16(t.y - __bfloat162float(h1))),
                pack_bf16(__float2bfloat16(t.z - __bfloat162float(h2)),
                          __float2bfloat16(t.w - __bfloat162float(h3))));
            int off = (r * KP + c4) * 2;
            *(uint2*)(smc + off)         = hh;
            *(uint2*)(smc + 18432 + off) = ll;
        }
    };
    auto cpw = [&](int kc, int buf) {
        // Wh for all 3 mats (192 rows)
        #pragma unroll
        for (int j = 0; j < 6; ++j) {
            int rem = tid + j * 256;              // 0..1535
            int nab = rem >> 3;                   // 0..191 = mat*64+n
            int c8  = rem & 7;
            CP16(sb + WB(buf) + nab * 144 + c8 * 16,
                 g_Wh + (size_t)nab * C_ + kc + c8 * 8);
        }
        // Wl for V only (64 rows)
        #pragma unroll
        for (int j = 0; j < 2; ++j) {
            int rem = tid + j * 256;              // 0..511
            int n   = rem >> 3;                   // 0..63
            int c8  = rem & 7;
            CP16(sb + WB(buf) + 27648 + n * 144 + c8 * 16,
                 g_Wl + (size_t)(2 * H_ * C_) + (size_t)n * C_ + kc + c8 * 8);
        }
        CP_COMMIT();
    };

    ldg_x(0);
    cpw(0, 0);

    #pragma unroll 1
    for (int c = 0; c < 16; ++c) {
        const int wbuf = c & 1;
        if (c < 15) cpw((c + 1) * 64, wbuf ^ 1);
        cvt_x();
        if (c < 15) ldg_x((c + 1) * 64);
        if (c < 15) asm volatile("cp.async.wait_group 1;" ::: "memory");
        else        asm volatile("cp.async.wait_group 0;" ::: "memory");
        __syncthreads();

        const uint32_t xa = sb + a_off;
        #pragma unroll
        for (int ks = 0; ks < 4; ++ks) {
            uint32_t ah0, ah1, ah2, ah3, al0, al1, al2, al3;
            ldsm4(ah0, ah1, ah2, ah3, xa + ks * 32);
            ldsm4(al0, al1, al2, al3, xa + 18432 + ks * 32);
            // Q, K: single-bf16
            #pragma unroll
            for (int mat = 0; mat < 2; ++mat) {
                #pragma unroll
                for (int nb2 = 0; nb2 < 4; ++nb2) {
                    uint32_t wa = sb + WB(wbuf) + (mat * 64 + nb2 * 16) * 144
                                + ks * 32 + b_off;
                    uint32_t bh0, bh1, bh2, bh3;
                    ldsm4(bh0, bh1, bh2, bh3, wa);
                    mma16816(acc[mat][nb2 * 2],     ah0, ah1, ah2, ah3, bh0, bh1);
                    mma16816(acc[mat][nb2 * 2 + 1], ah0, ah1, ah2, ah3, bh2, bh3);
                }
            }
            // V: full hi/lo split
            #pragma unroll
            for (int nb2 = 0; nb2 < 4; ++nb2) {
                uint32_t wa = sb + WB(wbuf) + (2 * 64 + nb2 * 16) * 144
                            + ks * 32 + b_off;
                uint32_t wl = sb + WB(wbuf) + 27648 + (nb2 * 16) * 144
                            + ks * 32 + b_off;
                uint32_t bh0, bh1, bh2, bh3, bl0, bl1, bl2, bl3;
                ldsm4(bh0, bh1, bh2, bh3, wa);
                ldsm4(bl0, bl1, bl2, bl3, wl);
                mma16816(acc[2][nb2 * 2],     ah0, ah1, ah2, ah3, bh0, bh1);
                mma16816(acc[2][nb2 * 2],     ah0, ah1, ah2, ah3, bl0, bl1);
                mma16816(acc[2][nb2 * 2],     al0, al1, al2, al3, bh0, bh1);
                mma16816(acc[2][nb2 * 2 + 1], ah0, ah1, ah2, ah3, bh2, bh3);
                mma16816(acc[2][nb2 * 2 + 1], ah0, ah1, ah2, ah3, bl2, bl3);
                mma16816(acc[2][nb2 * 2 + 1], al0, al1, al2, al3, bh2, bh3);
            }
        }
        __syncthreads();
    }

    // --- epilogue: Q (scaled 1/32) and K single bf16; V hi/lo ---
    const int g  = lane >> 2;
    const int tg = lane & 3;
    const int row = m0 + wid * 16 + g;
    #pragma unroll
    for (int mat = 0; mat < 3; ++mat) {
        const float* bias = (mat == 0) ? bq : (mat == 1) ? bk : bv;
        __nv_bfloat16* dh = (mat == 0) ? g_Qh : (mat == 1) ? g_Kh : g_Vh;
        const float scl = (mat == 0) ? 0.03125f : 1.0f;
        #pragma unroll
        for (int nb = 0; nb < 8; ++nb) {
            int col = nb * 8 + tg * 2;
            float b0 = __ldg(bias + col);
            float b1 = __ldg(bias + col + 1);
            float v0 = (acc[mat][nb][0] + b0) * scl;
            float v1 = (acc[mat][nb][1] + b1) * scl;
            float v2 = (acc[mat][nb][2] + b0) * scl;
            float v3 = (acc[mat][nb][3] + b1) * scl;
            __nv_bfloat16 h0 = __float2bfloat16(v0), h1 = __float2bfloat16(v1);
            __nv_bfloat16 h2 = __float2bfloat16(v2), h3 = __float2bfloat16(v3);
            size_t o0 = (size_t)row * H_ + col;
            size_t o1 = (size_t)(row + 8) * H_ + col;
            *(uint32_t*)(dh + o0) = pack_bf16(h0, h1);
            *(uint32_t*)(dh + o1) = pack_bf16(h2, h3);
            if (mat == 2) {
                *(uint32_t*)(g_Vl + o0) = pack_bf16(
                    __float2bfloat16(v0 - __bfloat162float(h0)),
                    __float2bfloat16(v1 - __bfloat162float(h1)));
                *(uint32_t*)(g_Vl + o1) = pack_bf16(
                    __float2bfloat16(v2 - __bfloat162float(h2)),
                    __float2bfloat16(v3 - __bfloat162float(h3)));
            }
        }
    }
}

// ---------------------------------------------------------------------------
// HMMA flash attention (unchanged from verified R7): 8 warps, even/odd
// k-tile split, single-bf16 S, hi/lo-split PV, 4-deep cp.async ring.
// ---------------------------------------------------------------------------
#define KVROW 144
#define ARR_B (64 * KVROW)        // 9216
#define TILE_B (3 * ARR_B)        // 27648: Kh,Vh,Vl
#define ATTN_SMEM (4 * TILE_B)    // 110592

__global__ __launch_bounds__(256) void attn_mma(float* __restrict__ out)
{
    extern __shared__ __align__(16) char smk[];
    const uint32_t sb = smem_u32(smk);
    float* msm = (float*)smk;
    const int tid  = threadIdx.x;
    const int lane = tid & 31;
    const int wid  = tid >> 5;
    const int wgrp = wid >> 2;
    const int wq4  = wid & 3;
    const int b    = blockIdx.y;
    const int px   = blockIdx.x;
    const int g    = lane >> 2;
    const int tg   = lane & 3;
    const int l8   = lane & 7;
    const int bgrp = lane >> 3;
    const int k_row = ((bgrp & 2) ? 8 : 0) + l8;
    const int k_col = (bgrp & 1) * 16;
    const int v_row = ((bgrp & 1) ? 8 : 0) + l8;
    const int v_col = (bgrp & 2) ? 16 : 0;
    const int bt0   = b * T_;

    #pragma unroll 1
    for (int half = 0; half < 2; ++half) {
        const int qt = half ? (31 - px) : px;
        const int q0 = qt * 64;
        const int nk = qt + 1;

        __syncthreads();

        uint32_t qh[4][4];
        {
            const uint32_t* qhp = (const uint32_t*)g_Qh + (size_t)(bt0 + q0 + wq4 * 16) * 32;
            #pragma unroll
            for (int ks = 0; ks < 4; ++ks) {
                int i0 = g * 32 + ks * 8 + tg;
                int i1 = (g + 8) * 32 + ks * 8 + tg;
                qh[ks][0] = qhp[i0];     qh[ks][1] = qhp[i1];
                qh[ks][2] = qhp[i0 + 4]; qh[ks][3] = qhp[i1 + 4];
            }
        }

        float m0 = -INFINITY, m1 = -INFINITY, l0 = 0.f, l1 = 0.f;
        float o[8][4];
        #pragma unroll
        for (int nb = 0; nb < 8; ++nb)
            o[nb][0] = o[nb][1] = o[nb][2] = o[nb][3] = 0.f;

        auto issue_tile = [&](int vt) {
            if (vt < nk) {
                uint32_t db = sb + (vt & 3) * TILE_B;
                size_t r0 = (size_t)(bt0 + vt * 64);
                #pragma unroll
                for (int j = 0; j < 6; ++j) {
                    int rem = tid + j * 256;
                    int arr = rem >> 9;
                    int idx = rem & 511;
                    int row = idx >> 3;
                    int c8  = idx & 7;
                    const __nv_bfloat16* sp = (arr == 0) ? g_Kh : (arr == 1) ? g_Vh : g_Vl;
                    CP16(db + arr * ARR_B + row * KVROW + c8 * 16,
                         sp + (r0 + row) * 64 + c8 * 8);
                }
            }
            CP_COMMIT();
        };

        issue_tile(0); issue_tile(1); issue_tile(2); issue_tile(3);

        const int iters = (nk + 1) >> 1;
        #pragma unroll 1
        for (int it = 0; it < iters; ++it) {
            asm volatile("cp.async.wait_group 2;" ::: "memory");
            __syncthreads();

            const int myt = 2 * it + wgrp;
            if (myt < nk) {
                const uint32_t kb_s = sb + (myt & 3) * TILE_B;
                const uint32_t kv_s = kb_s + ARR_B;

                float s[8][4];
                #pragma unroll
                for (int nb = 0; nb < 8; ++nb)
                    s[nb][0] = s[nb][1] = s[nb][2] = s[nb][3] = 0.f;

                #pragma unroll
                for (int ks = 0; ks < 4; ++ks) {
                    #pragma unroll
                    for (int np = 0; np < 4; ++np) {
                        uint32_t aH = kb_s + (np * 16 + k_row) * KVROW + k_col + ks * 32;
                        uint32_t bh0, bh1, bh2, bh3;
                        ldsm4(bh0, bh1, bh2, bh3, aH);
                        mma16816(s[np * 2],     qh[ks][0], qh[ks][1], qh[ks][2], qh[ks][3], bh0, bh1);
                        mma16816(s[np * 2 + 1], qh[ks][0], qh[ks][1], qh[ks][2], qh[ks][3], bh2, bh3);
                    }
                }

                if (myt == qt) {
                    const int r0 = wq4 * 16 + g;
                    const int r1 = r0 + 8;
                    #pragma unroll
                    for (int nb = 0; nb < 8; ++nb) {
                        int c0 = nb * 8 + tg * 2;
                        if (c0     > r0) s[nb][0] = -INFINITY;
                        if (c0 + 1 > r0) s[nb][1] = -INFINITY;
                        if (c0     > r1) s[nb][2] = -INFINITY;
                        if (c0 + 1 > r1) s[nb][3] = -INFINITY;
                    }
                }

                float rm0 = -INFINITY, rm1 = -INFINITY;
                #pragma unroll
                for (int nb = 0; nb < 8; ++nb) {
                    rm0 = fmaxf(rm0, fmaxf(s[nb][0], s[nb][1]));
                    rm1 = fmaxf(rm1, fmaxf(s[nb][2], s[nb][3]));
                }
                rm0 = fmaxf(rm0, __shfl_xor_sync(0xffffffffu, rm0, 1));
                rm0 = fmaxf(rm0, __shfl_xor_sync(0xffffffffu, rm0, 2));
                rm1 = fmaxf(rm1, __shfl_xor_sync(0xffffffffu, rm1, 1));
                rm1 = fmaxf(rm1, __shfl_xor_sync(0xffffffffu, rm1, 2));
                float mn0 = fmaxf(m0, rm0), mn1 = fmaxf(m1, rm1);
                float al0 = __expf(m0 - mn0), al1 = __expf(m1 - mn1);
                float rs0 = 0.f, rs1 = 0.f;
                #pragma unroll
                for (int nb = 0; nb < 8; ++nb) {
                    s[nb][0] = __expf(s[nb][0] - mn0);
                    s[nb][1] = __expf(s[nb][1] - mn0);
                    s[nb][2] = __expf(s[nb][2] - mn1);
                    s[nb][3] = __expf(s[nb][3] - mn1);
                    rs0 += s[nb][0] + s[nb][1];
                    rs1 += s[nb][2] + s[nb][3];
                }
                rs0 += __shfl_xor_sync(0xffffffffu, rs0, 1);
                rs0 += __shfl_xor_sync(0xffffffffu, rs0, 2);
                rs1 += __shfl_xor_sync(0xffffffffu, rs1, 1);
                rs1 += __shfl_xor_sync(0xffffffffu, rs1, 2);
                l0 = l0 * al0 + rs0; m0 = mn0;
                l1 = l1 * al1 + rs1; m1 = mn1;
                #pragma unroll
                for (int nb = 0; nb < 8; ++nb) {
                    o[nb][0] *= al0; o[nb][1] *= al0;
                    o[nb][2] *= al1; o[nb][3] *= al1;
                }

                #pragma unroll
                for (int ks = 0; ks < 4; ++ks) {
                    float p00 = s[2 * ks][0],     p01 = s[2 * ks][1];
                    float p02 = s[2 * ks][2],     p03 = s[2 * ks][3];
                    float p10 = s[2 * ks + 1][0], p11 = s[2 * ks + 1][1];
                    float p12 = s[2 * ks + 1][2], p13 = s[2 * ks + 1][3];
                    uint32_t pah0 = pk2(p00, p01), pah1 = pk2(p02, p03);
                    uint32_t pah2 = pk2(p10, p11), pah3 = pk2(p12, p13);
                    uint32_t pal0 = pk2(p00 - bfround(p00), p01 - bfround(p01));
                    uint32_t pal1 = pk2(p02 - bfround(p02), p03 - bfround(p03));
                    uint32_t pal2 = pk2(p10 - bfround(p10), p11 - bfround(p11));
                    uint32_t pal3 = pk2(p12 - bfround(p12), p13 - bfround(p13));
                    #pragma unroll
                    for (int hp = 0; hp < 4; ++hp) {
                        uint32_t aV = kv_s + (ks * 16 + v_row) * KVROW + v_col + hp * 32;
                        uint32_t vh0, vh1, vh2, vh3, vl0, vl1, vl2, vl3;
                        ldsm4t(vh0, vh1, vh2, vh3, aV);
                        ldsm4t(vl0, vl1, vl2, vl3, aV + ARR_B);
                        mma16816(o[hp * 2],     pah0, pah1, pah2, pah3, vh0, vh1);
                        mma16816(o[hp * 2],     pah0, pah1, pah2, pah3, vl0, vl1);
                        mma16816(o[hp * 2],     pal0, pal1, pal2, pal3, vh0, vh1);
                        mma16816(o[hp * 2 + 1], pah0, pah1, pah2, pah3, vh2, vh3);
                        mma16816(o[hp * 2 + 1], pah0, pah1, pah2, pah3, vl2, vl3);
                        mma16816(o[hp * 2 + 1], pal0, pal1, pal2, pal3, vh2, vh3);
                    }
                }
            }
            __syncthreads();
            issue_tile(2 * it + 4);
            issue_tile(2 * it + 5);
        }

        if (wgrp == 1) {
            float* p = msm + ((size_t)(wq4 * 32 + lane)) * 36;
            #pragma unroll
            for (int nb = 0; nb < 8; ++nb) {
                p[nb * 4 + 0] = o[nb][0]; p[nb * 4 + 1] = o[nb][1];
                p[nb * 4 + 2] = o[nb][2]; p[nb * 4 + 3] = o[nb][3];
            }
            p[32] = m0; p[33] = l0; p[34] = m1; p[35] = l1;
        }
        __syncthreads();
        if (wgrp == 0) {
            const float* p = msm + ((size_t)(wq4 * 32 + lane)) * 36;
            float om0 = p[32], ol0 = p[33], om1 = p[34], ol1 = p[35];
            float M0 = fmaxf(m0, om0), M1 = fmaxf(m1, om1);
            float A0 = __expf(m0 - M0), B0 = __expf(om0 - M0);
            float A1 = __expf(m1 - M1), B1 = __expf(om1 - M1);
            float inv0 = 1.0f / (l0 * A0 + ol0 * B0);
            float inv1 = 1.0f / (l1 * A1 + ol1 * B1);
            float* orow0 = out + (size_t)(bt0 + q0 + wq4 * 16 + g) * H_;
            float* orow1 = orow0 + 8 * H_;
            #pragma unroll
            for (int nb = 0; nb < 8; ++nb) {
                int col = nb * 8 + tg * 2;
                float e0 = (o[nb][0] * A0 + p[nb * 4 + 0] * B0) * inv0;
                float e1 = (o[nb][1] * A0 + p[nb * 4 + 1] * B0) * inv0;
                float e2 = (o[nb][2] * A1 + p[nb * 4 + 2] * B1) * inv1;
                float e3 = (o[nb][3] * A1 + p[nb * 4 + 3] * B1) * inv1;
                *(float2*)(orow0 + col) = make_float2(e0, e1);
                *(float2*)(orow1 + col) = make_float2(e2, e3);
            }
        }
    }
}

// ---------------------------------------------------------------------------
extern "C" void kernel_launch(void* const* d_in, const int* in_sizes, int n_in,
                              void* d_out, int out_size)
{
    const float* x  = (const float*)d_in[0];
    const float* wq = (const float*)d_in[1];
    const float* bq = (const float*)d_in[2];
    const float* wk = (const float*)d_in[3];
    const float* bk = (const float*)d_in[4];
    const float* wv = (const float*)d_in[5];
    const float* bv = (const float*)d_in[6];
    float* out = (float*)d_out;

    prep_w<<<(3 * H_ * C_ + 255) / 256, 256>>>(wq, wk, wv);

    cudaFuncSetAttribute(proj_mma, cudaFuncAttributeMaxDynamicSharedMemorySize, PROJ_SMEM);
    proj_mma<<<128, 256, PROJ_SMEM>>>(x, bq, bk, bv);

    cudaFuncSetAttribute(attn_mma, cudaFuncAttributeMaxDynamicSharedMemorySize, ATTN_SMEM);
    attn_mma<<<dim3(16, 8), 256, ATTN_SMEM>>>(out);
}

// round 13
// speedup vs baseline: 1.0209x; 1.0209x over previous
#include <cuda_runtime.h>
#include <cuda_bf16.h>
#include <math.h>
#include <stdint.h>

// Problem constants
#define B_   8
#define T_   2048
#define C_   1024
#define H_   64
#define NROW (B_ * T_)          // 16384

// Scratch: Q (pre-scaled 1/32) and K as single bf16; V as bf16 hi/lo.
__device__ __nv_bfloat16 g_Qh[NROW * H_];
__device__ __nv_bfloat16 g_Kh[NROW * H_];
__device__ __nv_bfloat16 g_Vh[NROW * H_], g_Vl[NROW * H_];
__device__ __nv_bfloat16 g_Wh[3 * H_ * C_];
__device__ __nv_bfloat16 g_Wl[3 * H_ * C_];

__device__ __forceinline__ uint32_t smem_u32(const void* p) {
    uint32_t a;
    asm("{ .reg .u64 t; cvta.to.shared.u64 t, %1; cvt.u32.u64 %0, t; }" : "=r"(a) : "l"(p));
    return a;
}
__device__ __forceinline__ void ldsm4(uint32_t& r0, uint32_t& r1, uint32_t& r2,
                                      uint32_t& r3, uint32_t addr) {
    asm volatile("ldmatrix.sync.aligned.m8n8.x4.shared.b16 {%0,%1,%2,%3}, [%4];"
                 : "=r"(r0), "=r"(r1), "=r"(r2), "=r"(r3) : "r"(addr));
}
__device__ __forceinline__ void ldsm4t(uint32_t& r0, uint32_t& r1, uint32_t& r2,
                                       uint32_t& r3, uint32_t addr) {
    asm volatile("ldmatrix.sync.aligned.m8n8.x4.trans.shared.b16 {%0,%1,%2,%3}, [%4];"
                 : "=r"(r0), "=r"(r1), "=r"(r2), "=r"(r3) : "r"(addr));
}
__device__ __forceinline__ void mma16816(float* d, uint32_t a0, uint32_t a1,
                                         uint32_t a2, uint32_t a3,
                                         uint32_t b0, uint32_t b1) {
    asm volatile("mma.sync.aligned.m16n8k16.row.col.f32.bf16.bf16.f32 "
                 "{%0,%1,%2,%3}, {%4,%5,%6,%7}, {%8,%9}, {%0,%1,%2,%3};"
                 : "+f"(d[0]), "+f"(d[1]), "+f"(d[2]), "+f"(d[3])
                 : "r"(a0), "r"(a1), "r"(a2), "r"(a3), "r"(b0), "r"(b1));
}
__device__ __forceinline__ uint32_t pk2(float lo, float hi) {
    uint32_t r;
    asm("cvt.rn.bf16x2.f32 %0, %1, %2;" : "=r"(r) : "f"(hi), "f"(lo));
    return r;
}
__device__ __forceinline__ float bfround(float v) {
    return __bfloat162float(__float2bfloat16(v));
}
__device__ __forceinline__ uint32_t pack_bf16(__nv_bfloat16 a, __nv_bfloat16 b) {
    __nv_bfloat162 t; t.x = a; t.y = b;
    return *(uint32_t*)&t;
}
#define CP16(dst, src) \
    asm volatile("cp.async.cg.shared.global [%0], [%1], 16;" :: "r"(dst), "l"(src) : "memory")
#define CP_COMMIT() asm volatile("cp.async.commit_group;" ::: "memory")

// ---------------------------------------------------------------------------
// Prep: split weights fp32 -> bf16 hi/lo, transpose [k][n] -> [mat][n][k]
// ---------------------------------------------------------------------------
__global__ void prep_w(const float* __restrict__ wq,
                       const float* __restrict__ wk,
                       const float* __restrict__ wv)
{
    int e = blockIdx.x * 256 + threadIdx.x;
    if (e >= 3 * H_ * C_) return;
    int mat = e / (H_ * C_);
    int r   = e % (H_ * C_);
    int n   = r / C_;
    int k   = r % C_;
    const float* w = (mat == 0) ? wq : (mat == 1) ? wk : wv;
    float v = w[k * H_ + n];
    __nv_bfloat16 h = __float2bfloat16(v);
    g_Wh[e] = h;
    g_Wl[e] = __float2bfloat16(v - __bfloat162float(h));
}

// ---------------------------------------------------------------------------
// Projection via mma.sync, software-pipelined.
//   Q/K: single-bf16 MMA (xh.wh). V: 3-way hi/lo split (accuracy-critical).
//   W: cp.async double buffer (Wl staged for V only); x: reg prefetch ->
//   single-buffered bf16 hi/lo smem. grid = 128 CTAs x 256 threads.
// ---------------------------------------------------------------------------
#define KP 72
#define XBUF_B 36864                           // xh(18432) + xl(18432)
#define WBUF_B 36864                           // Wh 3 mats (27648) + Wl V (9216)
#define WB(b)  (XBUF_B + (b) * WBUF_B)
#define PROJ_SMEM (XBUF_B + 2 * WBUF_B)        // 110592

__global__ __launch_bounds__(256) void proj_mma(
    const float* __restrict__ x,
    const float* __restrict__ bq,
    const float* __restrict__ bk,
    const float* __restrict__ bv)
{
    extern __shared__ char smc[];
    const uint32_t sb = smem_u32(smc);
    const int tid  = threadIdx.x;
    const int wid  = tid >> 5;
    const int lane = tid & 31;
    const int m0   = blockIdx.x * 128;

    float acc[3][8][4];
    #pragma unroll
    for (int m = 0; m < 3; ++m)
        #pragma unroll
        for (int n = 0; n < 8; ++n)
            #pragma unroll
            for (int i = 0; i < 4; ++i) acc[m][n][i] = 0.f;

    const int a_row  = lane & 15;
    const int a_half = lane >> 4;
    const uint32_t a_off = ((wid * 16 + a_row) * KP + a_half * 8) * 2;
    const int l8   = lane & 7;
    const int bgrp = lane >> 3;
    const int b_n  = ((bgrp & 2) ? 8 : 0) + l8;
    const int b_h  = bgrp & 1;
    const uint32_t b_off = (b_n * KP + b_h * 8) * 2;

    float4 X[8];
    auto ldg_x = [&](int kc) {
        #pragma unroll
        for (int it = 0; it < 8; ++it) {
            int u  = tid + it * 256;
            int r  = u >> 4;
            int c4 = (u & 15) << 2;
            X[it] = *(const float4*)(x + (size_t)(m0 + r) * C_ + kc + c4);
        }
    };
    auto cvt_x = [&]() {
        #pragma unroll
        for (int it = 0; it < 8; ++it) {
            int u  = tid + it * 256;
            int r  = u >> 4;
            int c4 = (u & 15) << 2;
            float4 t = X[it];
            __nv_bfloat16 h0 = __float2bfloat16(t.x);
            __nv_bfloat16 h1 = __float2bfloat16(t.y);
            __nv_bfloat16 h2 = __float2bfloat16(t.z);
            __nv_bfloat16 h3 = __float2bfloat16(t.w);
            uint2 hh = make_uint2(pack_bf16(h0, h1), pack_bf16(h2, h3));
            uint2 ll = make_uint2(
                pack_bf16(__float2bfloat16(t.x - __bfloat162float(h0)),
                          __float2bfloat16(t.y - __bfloat162float(h1))),
                pack_bf16(__float2bfloat16(t.z - __bfloat162float(h2)),
                          __float2bfloat16(t.w - __bfloat162float(h3))));
            int off = (r * KP + c4) * 2;
            *(uint2*)(smc + off)         = hh;
            *(uint2*)(smc + 18432 + off) = ll;
        }
    };
    auto cpw = [&](int kc, int buf) {
        // Wh for all 3 mats (192 rows)
        #pragma unroll
        for (int j = 0; j < 6; ++j) {
            int rem = tid + j * 256;              // 0..1535
            int nab = rem >> 3;                   // 0..191 = mat*64+n
            int c8  = rem & 7;
            CP16(sb + WB(buf) + nab * 144 + c8 * 16,
                 g_Wh + (size_t)nab * C_ + kc + c8 * 8);
        }
        // Wl for V only (64 rows)
        #pragma unroll
        for (int j = 0; j < 2; ++j) {
            int rem = tid + j * 256;              // 0..511
            int n   = rem >> 3;                   // 0..63
            int c8  = rem & 7;
            CP16(sb + WB(buf) + 27648 + n * 144 + c8 * 16,
                 g_Wl + (size_t)(2 * H_ * C_) + (size_t)n * C_ + kc + c8 * 8);
        }
        CP_COMMIT();
    };

    ldg_x(0);
    cpw(0, 0);

    #pragma unroll 1
    for (int c = 0; c < 16; ++c) {
        const int wbuf = c & 1;
        if (c < 15) cpw((c + 1) * 64, wbuf ^ 1);
        cvt_x();
        if (c < 15) ldg_x((c + 1) * 64);
        if (c < 15) asm volatile("cp.async.wait_group 1;" ::: "memory");
        else        asm volatile("cp.async.wait_group 0;" ::: "memory");
        __syncthreads();

        const uint32_t xa = sb + a_off;
        #pragma unroll
        for (int ks = 0; ks < 4; ++ks) {
            uint32_t ah0, ah1, ah2, ah3, al0, al1, al2, al3;
            ldsm4(ah0, ah1, ah2, ah3, xa + ks * 32);
            ldsm4(al0, al1, al2, al3, xa + 18432 + ks * 32);
            // Q, K: single-bf16
            #pragma unroll
            for (int mat = 0; mat < 2; ++mat) {
                #pragma unroll
                for (int nb2 = 0; nb2 < 4; ++nb2) {
                    uint32_t wa = sb + WB(wbuf) + (mat * 64 + nb2 * 16) * 144
                                + ks * 32 + b_off;
                    uint32_t bh0, bh1, bh2, bh3;
                    ldsm4(bh0, bh1, bh2, bh3, wa);
                    mma16816(acc[mat][nb2 * 2],     ah0, ah1, ah2, ah3, bh0, bh1);
                    mma16816(acc[mat][nb2 * 2 + 1], ah0, ah1, ah2, ah3, bh2, bh3);
                }
            }
            // V: full hi/lo split
            #pragma unroll
            for (int nb2 = 0; nb2 < 4; ++nb2) {
                uint32_t wa = sb + WB(wbuf) + (2 * 64 + nb2 * 16) * 144
                            + ks * 32 + b_off;
                uint32_t wl = sb + WB(wbuf) + 27648 + (nb2 * 16) * 144
                            + ks * 32 + b_off;
                uint32_t bh0, bh1, bh2, bh3, bl0, bl1, bl2, bl3;
                ldsm4(bh0, bh1, bh2, bh3, wa);
                ldsm4(bl0, bl1, bl2, bl3, wl);
                mma16816(acc[2][nb2 * 2],     ah0, ah1, ah2, ah3, bh0, bh1);
                mma16816(acc[2][nb2 * 2],     ah0, ah1, ah2, ah3, bl0, bl1);
                mma16816(acc[2][nb2 * 2],     al0, al1, al2, al3, bh0, bh1);
                mma16816(acc[2][nb2 * 2 + 1], ah0, ah1, ah2, ah3, bh2, bh3);
                mma16816(acc[2][nb2 * 2 + 1], ah0, ah1, ah2, ah3, bl2, bl3);
                mma16816(acc[2][nb2 * 2 + 1], al0, al1, al2, al3, bh2, bh3);
            }
        }
        __syncthreads();
    }

    // --- epilogue: Q (scaled 1/32) and K single bf16; V hi/lo ---
    const int g  = lane >> 2;
    const int tg = lane & 3;
    const int row = m0 + wid * 16 + g;
    #pragma unroll
    for (int mat = 0; mat < 3; ++mat) {
        const float* bias = (mat == 0) ? bq : (mat == 1) ? bk : bv;
        __nv_bfloat16* dh = (mat == 0) ? g_Qh : (mat == 1) ? g_Kh : g_Vh;
        const float scl = (mat == 0) ? 0.03125f : 1.0f;
        #pragma unroll
        for (int nb = 0; nb < 8; ++nb) {
            int col = nb * 8 + tg * 2;
            float b0 = __ldg(bias + col);
            float b1 = __ldg(bias + col + 1);
            float v0 = (acc[mat][nb][0] + b0) * scl;
            float v1 = (acc[mat][nb][1] + b1) * scl;
            float v2 = (acc[mat][nb][2] + b0) * scl;
            float v3 = (acc[mat][nb][3] + b1) * scl;
            __nv_bfloat16 h0 = __float2bfloat16(v0), h1 = __float2bfloat16(v1);
            __nv_bfloat16 h2 = __float2bfloat16(v2), h3 = __float2bfloat16(v3);
            size_t o0 = (size_t)row * H_ + col;
            size_t o1 = (size_t)(row + 8) * H_ + col;
            *(uint32_t*)(dh + o0) = pack_bf16(h0, h1);
            *(uint32_t*)(dh + o1) = pack_bf16(h2, h3);
            if (mat == 2) {
                *(uint32_t*)(g_Vl + o0) = pack_bf16(
                    __float2bfloat16(v0 - __bfloat162float(h0)),
                    __float2bfloat16(v1 - __bfloat162float(h1)));
                *(uint32_t*)(g_Vl + o1) = pack_bf16(
                    __float2bfloat16(v2 - __bfloat162float(h2)),
                    __float2bfloat16(v3 - __bfloat162float(h3)));
            }
        }
    }
}

// ---------------------------------------------------------------------------
// HMMA flash attention (unchanged from verified R7): 8 warps, even/odd
// k-tile split, single-bf16 S, hi/lo-split PV, 4-deep cp.async ring.
// ---------------------------------------------------------------------------
#define KVROW 144
#define ARR_B (64 * KVROW)        // 9216
#define TILE_B (3 * ARR_B)        // 27648: Kh,Vh,Vl
#define ATTN_SMEM (4 * TILE_B)    // 110592

__global__ __launch_bounds__(256) void attn_mma(float* __restrict__ out)
{
    extern __shared__ __align__(16) char smk[];
    const uint32_t sb = smem_u32(smk);
    float* msm = (float*)smk;
    const int tid  = threadIdx.x;
    const int lane = tid & 31;
    const int wid  = tid >> 5;
    const int wgrp = wid >> 2;
    const int wq4  = wid & 3;
    const int b    = blockIdx.y;
    const int px   = blockIdx.x;
    const int g    = lane >> 2;
    const int tg   = lane & 3;
    const int l8   = lane & 7;
    const int bgrp = lane >> 3;
    const int k_row = ((bgrp & 2) ? 8 : 0) + l8;
    const int k_col = (bgrp & 1) * 16;
    const int v_row = ((bgrp & 1) ? 8 : 0) + l8;
    const int v_col = (bgrp & 2) ? 16 : 0;
    const int bt0   = b * T_;

    #pragma unroll 1
    for (int half = 0; half < 2; ++half) {
        const int qt = half ? (31 - px) : px;
        const int q0 = qt * 64;
        const int nk = qt + 1;

        __syncthreads();

        uint32_t qh[4][4];
        {
            const uint32_t* qhp = (const uint32_t*)g_Qh + (size_t)(bt0 + q0 + wq4 * 16) * 32;
            #pragma unroll
            for (int ks = 0; ks < 4; ++ks) {
                int i0 = g * 32 + ks * 8 + tg;
                int i1 = (g + 8) * 32 + ks * 8 + tg;
                qh[ks][0] = qhp[i0];     qh[ks][1] = qhp[i1];
                qh[ks][2] = qhp[i0 + 4]; qh[ks][3] = qhp[i1 + 4];
            }
        }

        float m0 = -INFINITY, m1 = -INFINITY, l0 = 0.f, l1 = 0.f;
        float o[8][4];
        #pragma unroll
        for (int nb = 0; nb < 8; ++nb)
            o[nb][0] = o[nb][1] = o[nb][2] = o[nb][3] = 0.f;

        auto issue_tile = [&](int vt) {
            if (vt < nk) {
                uint32_t db = sb + (vt & 3) * TILE_B;
                size_t r0 = (size_t)(bt0 + vt * 64);
                #pragma unroll
                for (int j = 0; j < 6; ++j) {
                    int rem = tid + j * 256;
                    int arr = rem >> 9;
                    int idx = rem & 511;
                    int row = idx >> 3;
                    int c8  = idx & 7;
                    const __nv_bfloat16* sp = (arr == 0) ? g_Kh : (arr == 1) ? g_Vh : g_Vl;
                    CP16(db + arr * ARR_B + row * KVROW + c8 * 16,
                         sp + (r0 + row) * 64 + c8 * 8);
                }
            }
            CP_COMMIT();
        };

        issue_tile(0); issue_tile(1); issue_tile(2); issue_tile(3);

        const int iters = (nk + 1) >> 1;
        #pragma unroll 1
        for (int it = 0; it < iters; ++it) {
            asm volatile("cp.async.wait_group 2;" ::: "memory");
            __syncthreads();

            const int myt = 2 * it + wgrp;
            if (myt < nk) {
                const uint32_t kb_s = sb + (myt & 3) * TILE_B;
                const uint32_t kv_s = kb_s + ARR_B;

                float s[8][4];
                #pragma unroll
                for (int nb = 0; nb < 8; ++nb)
                    s[nb][0] = s[nb][1] = s[nb][2] = s[nb][3] = 0.f;

                #pragma unroll
                for (int ks = 0; ks < 4; ++ks) {
                    #pragma unroll
                    for (int np = 0; np < 4; ++np) {
                        uint32_t aH = kb_s + (np * 16 + k_row) * KVROW + k_col + ks * 32;
                        uint32_t bh0, bh1, bh2, bh3;
                        ldsm4(bh0, bh1, bh2, bh3, aH);
                        mma16816(s[np * 2],     qh[ks][0], qh[ks][1], qh[ks][2], qh[ks][3], bh0, bh1);
                        mma16816(s[np * 2 + 1], qh[ks][0], qh[ks][1], qh[ks][2], qh[ks][3], bh2, bh3);
                    }
                }

                if (myt == qt) {
                    const int r0 = wq4 * 16 + g;
                    const int r1 = r0 + 8;
                    #pragma unroll
                    for (int nb = 0; nb < 8; ++nb) {
                        int c0 = nb * 8 + tg * 2;
                        if (c0     > r0) s[nb][0] = -INFINITY;
                        if (c0 + 1 > r0) s[nb][1] = -INFINITY;
                        if (c0     > r1) s[nb][2] = -INFINITY;
                        if (c0 + 1 > r1) s[nb][3] = -INFINITY;
                    }
                }

                float rm0 = -INFINITY, rm1 = -INFINITY;
                #pragma unroll
                for (int nb = 0; nb < 8; ++nb) {
                    rm0 = fmaxf(rm0, fmaxf(s[nb][0], s[nb][1]));
                    rm1 = fmaxf(rm1, fmaxf(s[nb][2], s[nb][3]));
                }
                rm0 = fmaxf(rm0, __shfl_xor_sync(0xffffffffu, rm0, 1));
                rm0 = fmaxf(rm0, __shfl_xor_sync(0xffffffffu, rm0, 2));
                rm1 = fmaxf(rm1, __shfl_xor_sync(0xffffffffu, rm1, 1));
                rm1 = fmaxf(rm1, __shfl_xor_sync(0xffffffffu, rm1, 2));
                float mn0 = fmaxf(m0, rm0), mn1 = fmaxf(m1, rm1);
                float al0 = __expf(m0 - mn0), al1 = __expf(m1 - mn1);
                float rs0 = 0.f, rs1 = 0.f;
                #pragma unroll
                for (int nb = 0; nb < 8; ++nb) {
                    s[nb][0] = __expf(s[nb][0] - mn0);
                    s[nb][1] = __expf(s[nb][1] - mn0);
                    s[nb][2] = __expf(s[nb][2] - mn1);
                    s[nb][3] = __expf(s[nb][3] - mn1);
                    rs0 += s[nb][0] + s[nb][1];
                    rs1 += s[nb][2] + s[nb][3];
                }
                rs0 += __shfl_xor_sync(0xffffffffu, rs0, 1);
                rs0 += __shfl_xor_sync(0xffffffffu, rs0, 2);
                rs1 += __shfl_xor_sync(0xffffffffu, rs1, 1);
                rs1 += __shfl_xor_sync(0xffffffffu, rs1, 2);
                l0 = l0 * al0 + rs0; m0 = mn0;
                l1 = l1 * al1 + rs1; m1 = mn1;
                #pragma unroll
                for (int nb = 0; nb < 8; ++nb) {
                    o[nb][0] *= al0; o[nb][1] *= al0;
                    o[nb][2] *= al1; o[nb][3] *= al1;
                }

                #pragma unroll
                for (int ks = 0; ks < 4; ++ks) {
                    float p00 = s[2 * ks][0],     p01 = s[2 * ks][1];
                    float p02 = s[2 * ks][2],     p03 = s[2 * ks][3];
                    float p10 = s[2 * ks + 1][0], p11 = s[2 * ks + 1][1];
                    float p12 = s[2 * ks + 1][2], p13 = s[2 * ks + 1][3];
                    uint32_t pah0 = pk2(p00, p01), pah1 = pk2(p02, p03);
                    uint32_t pah2 = pk2(p10, p11), pah3 = pk2(p12, p13);
                    uint32_t pal0 = pk2(p00 - bfround(p00), p01 - bfround(p01));
                    uint32_t pal1 = pk2(p02 - bfround(p02), p03 - bfround(p03));
                    uint32_t pal2 = pk2(p10 - bfround(p10), p11 - bfround(p11));
                    uint32_t pal3 = pk2(p12 - bfround(p12), p13 - bfround(p13));
                    #pragma unroll
                    for (int hp = 0; hp < 4; ++hp) {
                        uint32_t aV = kv_s + (ks * 16 + v_row) * KVROW + v_col + hp * 32;
                        uint32_t vh0, vh1, vh2, vh3, vl0, vl1, vl2, vl3;
                        ldsm4t(vh0, vh1, vh2, vh3, aV);
                        ldsm4t(vl0, vl1, vl2, vl3, aV + ARR_B);
                        mma16816(o[hp * 2],     pah0, pah1, pah2, pah3, vh0, vh1);
                        mma16816(o[hp * 2],     pah0, pah1, pah2, pah3, vl0, vl1);
                        mma16816(o[hp * 2],     pal0, pal1, pal2, pal3, vh0, vh1);
                        mma16816(o[hp * 2 + 1], pah0, pah1, pah2, pah3, vh2, vh3);
                        mma16816(o[hp * 2 + 1], pah0, pah1, pah2, pah3, vl2, vl3);
                        mma16816(o[hp * 2 + 1], pal0, pal1, pal2, pal3, vh2, vh3);
                    }
                }
            }
            __syncthreads();
            issue_tile(2 * it + 4);
            issue_tile(2 * it + 5);
        }

        if (wgrp == 1) {
            float* p = msm + ((size_t)(wq4 * 32 + lane)) * 36;
            #pragma unroll
            for (int nb = 0; nb < 8; ++nb) {
                p[nb * 4 + 0] = o[nb][0]; p[nb * 4 + 1] = o[nb][1];
                p[nb * 4 + 2] = o[nb][2]; p[nb * 4 + 3] = o[nb][3];
            }
            p[32] = m0; p[33] = l0; p[34] = m1; p[35] = l1;
        }
        __syncthreads();
        if (wgrp == 0) {
            const float* p = msm + ((size_t)(wq4 * 32 + lane)) * 36;
            float om0 = p[32], ol0 = p[33], om1 = p[34], ol1 = p[35];
            float M0 = fmaxf(m0, om0), M1 = fmaxf(m1, om1);
            float A0 = __expf(m0 - M0), B0 = __expf(om0 - M0);
            float A1 = __expf(m1 - M1), B1 = __expf(om1 - M1);
            float inv0 = 1.0f / (l0 * A0 + ol0 * B0);
            float inv1 = 1.0f / (l1 * A1 + ol1 * B1);
            float* orow0 = out + (size_t)(bt0 + q0 + wq4 * 16 + g) * H_;
            float* orow1 = orow0 + 8 * H_;
            #pragma unroll
            for (int nb = 0; nb < 8; ++nb) {
                int col = nb * 8 + tg * 2;
                float e0 = (o[nb][0] * A0 + p[nb * 4 + 0] * B0) * inv0;
                float e1 = (o[nb][1] * A0 + p[nb * 4 + 1] * B0) * inv0;
                float e2 = (o[nb][2] * A1 + p[nb * 4 + 2] * B1) * inv1;
                float e3 = (o[nb][3] * A1 + p[nb * 4 + 3] * B1) * inv1;
                *(float2*)(orow0 + col) = make_float2(e0, e1);
                *(float2*)(orow1 + col) = make_float2(e2, e3);
            }
        }
    }
}

// ---------------------------------------------------------------------------
extern "C" void kernel_launch(void* const* d_in, const int* in_sizes, int n_in,
                              void* d_out, int out_size)
{
    const float* x  = (const float*)d_in[0];
    const float* wq = (const float*)d_in[1];
    const float* bq = (const float*)d_in[2];
    const float* wk = (const float*)d_in[3];
    const float* bk = (const float*)d_in[4];
    const float* wv = (const float*)d_in[5];
    const float* bv = (const float*)d_in[6];
    float* out = (float*)d_out;

    prep_w<<<(3 * H_ * C_ + 255) / 256, 256>>>(wq, wk, wv);

    cudaFuncSetAttribute(proj_mma, cudaFuncAttributeMaxDynamicSharedMemorySize, PROJ_SMEM);
    proj_mma<<<128, 256, PROJ_SMEM>>>(x, bq, bk, bv);

    cudaFuncSetAttribute(attn_mma, cudaFuncAttributeMaxDynamicSharedMemorySize, ATTN_SMEM);
    attn_mma<<<dim3(16, 8), 256, ATTN_SMEM>>>(out);
}

// round 14
// speedup vs baseline: 1.0217x; 1.0007x over previous
#include <cuda_runtime.h>
#include <cuda_bf16.h>
#include <math.h>
#include <stdint.h>

// Problem constants
#define B_   8
#define T_   2048
#define C_   1024
#define H_   64
#define NROW (B_ * T_)          // 16384

// Scratch: Q (pre-scaled 1/32) and K as single bf16; V as bf16 hi/lo.
__device__ __nv_bfloat16 g_Qh[NROW * H_];
__device__ __nv_bfloat16 g_Kh[NROW * H_];
__device__ __nv_bfloat16 g_Vh[NROW * H_], g_Vl[NROW * H_];
__device__ __nv_bfloat16 g_Wh[3 * H_ * C_];
__device__ __nv_bfloat16 g_Wl[3 * H_ * C_];

__device__ __forceinline__ uint32_t smem_u32(const void* p) {
    uint32_t a;
    asm("{ .reg .u64 t; cvta.to.shared.u64 t, %1; cvt.u32.u64 %0, t; }" : "=r"(a) : "l"(p));
    return a;
}
__device__ __forceinline__ void ldsm4(uint32_t& r0, uint32_t& r1, uint32_t& r2,
                                      uint32_t& r3, uint32_t addr) {
    asm volatile("ldmatrix.sync.aligned.m8n8.x4.shared.b16 {%0,%1,%2,%3}, [%4];"
                 : "=r"(r0), "=r"(r1), "=r"(r2), "=r"(r3) : "r"(addr));
}
__device__ __forceinline__ void ldsm4t(uint32_t& r0, uint32_t& r1, uint32_t& r2,
                                       uint32_t& r3, uint32_t addr) {
    asm volatile("ldmatrix.sync.aligned.m8n8.x4.trans.shared.b16 {%0,%1,%2,%3}, [%4];"
                 : "=r"(r0), "=r"(r1), "=r"(r2), "=r"(r3) : "r"(addr));
}
__device__ __forceinline__ void mma16816(float* d, uint32_t a0, uint32_t a1,
                                         uint32_t a2, uint32_t a3,
                                         uint32_t b0, uint32_t b1) {
    asm volatile("mma.sync.aligned.m16n8k16.row.col.f32.bf16.bf16.f32 "
                 "{%0,%1,%2,%3}, {%4,%5,%6,%7}, {%8,%9}, {%0,%1,%2,%3};"
                 : "+f"(d[0]), "+f"(d[1]), "+f"(d[2]), "+f"(d[3])
                 : "r"(a0), "r"(a1), "r"(a2), "r"(a3), "r"(b0), "r"(b1));
}
__device__ __forceinline__ uint32_t pk2(float lo, float hi) {
    uint32_t r;
    asm("cvt.rn.bf16x2.f32 %0, %1, %2;" : "=r"(r) : "f"(hi), "f"(lo));
    return r;
}
__device__ __forceinline__ float bfround(float v) {
    return __bfloat162float(__float2bfloat16(v));
}
__device__ __forceinline__ uint32_t pack_bf16(__nv_bfloat16 a, __nv_bfloat16 b) {
    __nv_bfloat162 t; t.x = a; t.y = b;
    return *(uint32_t*)&t;
}
#define CP16(dst, src) \
    asm volatile("cp.async.cg.shared.global [%0], [%1], 16;" :: "r"(dst), "l"(src) : "memory")
#define CP_COMMIT() asm volatile("cp.async.commit_group;" ::: "memory")

// ---------------------------------------------------------------------------
// Prep: split weights fp32 -> bf16 hi/lo, transpose [k][n] -> [mat][n][k]
// ---------------------------------------------------------------------------
__global__ void prep_w(const float* __restrict__ wq,
                       const float* __restrict__ wk,
                       const float* __restrict__ wv)
{
    int e = blockIdx.x * 256 + threadIdx.x;
    if (e >= 3 * H_ * C_) return;
    int mat = e / (H_ * C_);
    int r   = e % (H_ * C_);
    int n   = r / C_;
    int k   = r % C_;
    const float* w = (mat == 0) ? wq : (mat == 1) ? wk : wv;
    float v = w[k * H_ + n];
    __nv_bfloat16 h = __float2bfloat16(v);
    g_Wh[e] = h;
    g_Wl[e] = __float2bfloat16(v - __bfloat162float(h));
}

// ---------------------------------------------------------------------------
// Projection via mma.sync, software-pipelined.
//   Q/K: single-bf16 MMA (xh.wh). V: 3-way hi/lo split (accuracy-critical).
//   W: cp.async double buffer (Wl staged for V only); x: reg prefetch ->
//   single-buffered bf16 hi/lo smem. grid = 128 CTAs x 256 threads.
// ---------------------------------------------------------------------------
#define KP 72
#define XBUF_B 36864                           // xh(18432) + xl(18432)
#define WBUF_B 36864                           // Wh 3 mats (27648) + Wl V (9216)
#define WB(b)  (XBUF_B + (b) * WBUF_B)
#define PROJ_SMEM (XBUF_B + 2 * WBUF_B)        // 110592

__global__ __launch_bounds__(256) void proj_mma(
    const float* __restrict__ x,
    const float* __restrict__ bq,
    const float* __restrict__ bk,
    const float* __restrict__ bv)
{
    extern __shared__ char smc[];
    const uint32_t sb = smem_u32(smc);
    const int tid  = threadIdx.x;
    const int wid  = tid >> 5;
    const int lane = tid & 31;
    const int m0   = blockIdx.x * 128;

    float acc[3][8][4];
    #pragma unroll
    for (int m = 0; m < 3; ++m)
        #pragma unroll
        for (int n = 0; n < 8; ++n)
            #pragma unroll
            for (int i = 0; i < 4; ++i) acc[m][n][i] = 0.f;

    const int a_row  = lane & 15;
    const int a_half = lane >> 4;
    const uint32_t a_off = ((wid * 16 + a_row) * KP + a_half * 8) * 2;
    const int l8   = lane & 7;
    const int bgrp = lane >> 3;
    const int b_n  = ((bgrp & 2) ? 8 : 0) + l8;
    const int b_h  = bgrp & 1;
    const uint32_t b_off = (b_n * KP + b_h * 8) * 2;

    float4 X[8];
    auto ldg_x = [&](int kc) {
        #pragma unroll
        for (int it = 0; it < 8; ++it) {
            int u  = tid + it * 256;
            int r  = u >> 4;
            int c4 = (u & 15) << 2;
            X[it] = *(const float4*)(x + (size_t)(m0 + r) * C_ + kc + c4);
        }
    };
    auto cvt_x = [&]() {
        #pragma unroll
        for (int it = 0; it < 8; ++it) {
            int u  = tid + it * 256;
            int r  = u >> 4;
            int c4 = (u & 15) << 2;
            float4 t = X[it];
            __nv_bfloat16 h0 = __float2bfloat16(t.x);
            __nv_bfloat16 h1 = __float2bfloat16(t.y);
            __nv_bfloat16 h2 = __float2bfloat16(t.z);
            __nv_bfloat16 h3 = __float2bfloat16(t.w);
            uint2 hh = make_uint2(pack_bf16(h0, h1), pack_bf16(h2, h3));
            uint2 ll = make_uint2(
                pack_bf16(__float2bfloat16(t.x - __bfloat162float(h0)),
                          __float2bfloat16(t.y - __bfloat162float(h1))),
                pack_bf16(__float2bfloat16(t.z - __bfloat162float(h2)),
                          __float2bfloat16(t.w - __bfloat162float(h3))));
            int off = (r * KP + c4) * 2;
            *(uint2*)(smc + off)         = hh;
            *(uint2*)(smc + 18432 + off) = ll;
        }
    };
    auto cpw = [&](int kc, int buf) {
        // Wh for all 3 mats (192 rows)
        #pragma unroll
        for (int j = 0; j < 6; ++j) {
            int rem = tid + j * 256;              // 0..1535
            int nab = rem >> 3;                   // 0..191 = mat*64+n
            int c8  = rem & 7;
            CP16(sb + WB(buf) + nab * 144 + c8 * 16,
                 g_Wh + (size_t)nab * C_ + kc + c8 * 8);
        }
        // Wl for V only (64 rows)
        #pragma unroll
        for (int j = 0; j < 2; ++j) {
            int rem = tid + j * 256;              // 0..511
            int n   = rem >> 3;                   // 0..63
            int c8  = rem & 7;
            CP16(sb + WB(buf) + 27648 + n * 144 + c8 * 16,
                 g_Wl + (size_t)(2 * H_ * C_) + (size_t)n * C_ + kc + c8 * 8);
        }
        CP_COMMIT();
    };

    ldg_x(0);
    cpw(0, 0);

    #pragma unroll 1
    for (int c = 0; c < 16; ++c) {
        const int wbuf = c & 1;
        if (c < 15) cpw((c + 1) * 64, wbuf ^ 1);
        cvt_x();
        if (c < 15) ldg_x((c + 1) * 64);
        if (c < 15) asm volatile("cp.async.wait_group 1;" ::: "memory");
        else        asm volatile("cp.async.wait_group 0;" ::: "memory");
        __syncthreads();

        const uint32_t xa = sb + a_off;
        #pragma unroll
        for (int ks = 0; ks < 4; ++ks) {
            uint32_t ah0, ah1, ah2, ah3, al0, al1, al2, al3;
            ldsm4(ah0, ah1, ah2, ah3, xa + ks * 32);
            ldsm4(al0, al1, al2, al3, xa + 18432 + ks * 32);
            // Q, K: single-bf16
            #pragma unroll
            for (int mat = 0; mat < 2; ++mat) {
                #pragma unroll
                for (int nb2 = 0; nb2 < 4; ++nb2) {
                    uint32_t wa = sb + WB(wbuf) + (mat * 64 + nb2 * 16) * 144
                                + ks * 32 + b_off;
                    uint32_t bh0, bh1, bh2, bh3;
                    ldsm4(bh0, bh1, bh2, bh3, wa);
                    mma16816(acc[mat][nb2 * 2],     ah0, ah1, ah2, ah3, bh0, bh1);
                    mma16816(acc[mat][nb2 * 2 + 1], ah0, ah1, ah2, ah3, bh2, bh3);
                }
            }
            // V: full hi/lo split
            #pragma unroll
            for (int nb2 = 0; nb2 < 4; ++nb2) {
                uint32_t wa = sb + WB(wbuf) + (2 * 64 + nb2 * 16) * 144
                            + ks * 32 + b_off;
                uint32_t wl = sb + WB(wbuf) + 27648 + (nb2 * 16) * 144
                            + ks * 32 + b_off;
                uint32_t bh0, bh1, bh2, bh3, bl0, bl1, bl2, bl3;
                ldsm4(bh0, bh1, bh2, bh3, wa);
                ldsm4(bl0, bl1, bl2, bl3, wl);
                mma16816(acc[2][nb2 * 2],     ah0, ah1, ah2, ah3, bh0, bh1);
                mma16816(acc[2][nb2 * 2],     ah0, ah1, ah2, ah3, bl0, bl1);
                mma16816(acc[2][nb2 * 2],     al0, al1, al2, al3, bh0, bh1);
                mma16816(acc[2][nb2 * 2 + 1], ah0, ah1, ah2, ah3, bh2, bh3);
                mma16816(acc[2][nb2 * 2 + 1], ah0, ah1, ah2, ah3, bl2, bl3);
                mma16816(acc[2][nb2 * 2 + 1], al0, al1, al2, al3, bh2, bh3);
            }
        }
        __syncthreads();
    }

    // --- epilogue: Q (scaled 1/32) and K single bf16; V hi/lo ---
    const int g  = lane >> 2;
    const int tg = lane & 3;
    const int row = m0 + wid * 16 + g;
    #pragma unroll
    for (int mat = 0; mat < 3; ++mat) {
        const float* bias = (mat == 0) ? bq : (mat == 1) ? bk : bv;
        __nv_bfloat16* dh = (mat == 0) ? g_Qh : (mat == 1) ? g_Kh : g_Vh;
        const float scl = (mat == 0) ? 0.03125f : 1.0f;
        #pragma unroll
        for (int nb = 0; nb < 8; ++nb) {
            int col = nb * 8 + tg * 2;
            float b0 = __ldg(bias + col);
            float b1 = __ldg(bias + col + 1);
            float v0 = (acc[mat][nb][0] + b0) * scl;
            float v1 = (acc[mat][nb][1] + b1) * scl;
            float v2 = (acc[mat][nb][2] + b0) * scl;
            float v3 = (acc[mat][nb][3] + b1) * scl;
            __nv_bfloat16 h0 = __float2bfloat16(v0), h1 = __float2bfloat16(v1);
            __nv_bfloat16 h2 = __float2bfloat16(v2), h3 = __float2bfloat16(v3);
            size_t o0 = (size_t)row * H_ + col;
            size_t o1 = (size_t)(row + 8) * H_ + col;
            *(uint32_t*)(dh + o0) = pack_bf16(h0, h1);
            *(uint32_t*)(dh + o1) = pack_bf16(h2, h3);
            if (mat == 2) {
                *(uint32_t*)(g_Vl + o0) = pack_bf16(
                    __float2bfloat16(v0 - __bfloat162float(h0)),
                    __float2bfloat16(v1 - __bfloat162float(h1)));
                *(uint32_t*)(g_Vl + o1) = pack_bf16(
                    __float2bfloat16(v2 - __bfloat162float(h2)),
                    __float2bfloat16(v3 - __bfloat162float(h3)));
            }
        }
    }
}

// ---------------------------------------------------------------------------
// HMMA flash attention (unchanged from verified R7): 8 warps, even/odd
// k-tile split, single-bf16 S, hi/lo-split PV, 4-deep cp.async ring.
// ---------------------------------------------------------------------------
#define KVROW 144
#define ARR_B (64 * KVROW)        // 9216
#define TILE_B (3 * ARR_B)        // 27648: Kh,Vh,Vl
#define ATTN_SMEM (4 * TILE_B)    // 110592

__global__ __launch_bounds__(256) void attn_mma(float* __restrict__ out)
{
    extern __shared__ __align__(16) char smk[];
    const uint32_t sb = smem_u32(smk);
    float* msm = (float*)smk;
    const int tid  = threadIdx.x;
    const int lane = tid & 31;
    const int wid  = tid >> 5;
    const int wgrp = wid >> 2;
    const int wq4  = wid & 3;
    const int b    = blockIdx.y;
    const int px   = blockIdx.x;
    const int g    = lane >> 2;
    const int tg   = lane & 3;
    const int l8   = lane & 7;
    const int bgrp = lane >> 3;
    const int k_row = ((bgrp & 2) ? 8 : 0) + l8;
    const int k_col = (bgrp & 1) * 16;
    const int v_row = ((bgrp & 1) ? 8 : 0) + l8;
    const int v_col = (bgrp & 2) ? 16 : 0;
    const int bt0   = b * T_;

    #pragma unroll 1
    for (int half = 0; half < 2; ++half) {
        const int qt = half ? (31 - px) : px;
        const int q0 = qt * 64;
        const int nk = qt + 1;

        __syncthreads();

        uint32_t qh[4][4];
        {
            const uint32_t* qhp = (const uint32_t*)g_Qh + (size_t)(bt0 + q0 + wq4 * 16) * 32;
            #pragma unroll
            for (int ks = 0; ks < 4; ++ks) {
                int i0 = g * 32 + ks * 8 + tg;
                int i1 = (g + 8) * 32 + ks * 8 + tg;
                qh[ks][0] = qhp[i0];     qh[ks][1] = qhp[i1];
                qh[ks][2] = qhp[i0 + 4]; qh[ks][3] = qhp[i1 + 4];
            }
        }

        float m0 = -INFINITY, m1 = -INFINITY, l0 = 0.f, l1 = 0.f;
        float o[8][4];
        #pragma unroll
        for (int nb = 0; nb < 8; ++nb)
            o[nb][0] = o[nb][1] = o[nb][2] = o[nb][3] = 0.f;

        auto issue_tile = [&](int vt) {
            if (vt < nk) {
                uint32_t db = sb + (vt & 3) * TILE_B;
                size_t r0 = (size_t)(bt0 + vt * 64);
                #pragma unroll
                for (int j = 0; j < 6; ++j) {
                    int rem = tid + j * 256;
                    int arr = rem >> 9;
                    int idx = rem & 511;
                    int row = idx >> 3;
                    int c8  = idx & 7;
                    const __nv_bfloat16* sp = (arr == 0) ? g_Kh : (arr == 1) ? g_Vh : g_Vl;
                    CP16(db + arr * ARR_B + row * KVROW + c8 * 16,
                         sp + (r0 + row) * 64 + c8 * 8);
                }
            }
            CP_COMMIT();
        };

        issue_tile(0); issue_tile(1); issue_tile(2); issue_tile(3);

        const int iters = (nk + 1) >> 1;
        #pragma unroll 1
        for (int it = 0; it < iters; ++it) {
            asm volatile("cp.async.wait_group 2;" ::: "memory");
            __syncthreads();

            const int myt = 2 * it + wgrp;
            if (myt < nk) {
                const uint32_t kb_s = sb + (myt & 3) * TILE_B;
                const uint32_t kv_s = kb_s + ARR_B;

                float s[8][4];
                #pragma unroll
                for (int nb = 0; nb < 8; ++nb)
                    s[nb][0] = s[nb][1] = s[nb][2] = s[nb][3] = 0.f;

                #pragma unroll
                for (int ks = 0; ks < 4; ++ks) {
                    #pragma unroll
                    for (int np = 0; np < 4; ++np) {
                        uint32_t aH = kb_s + (np * 16 + k_row) * KVROW + k_col + ks * 32;
                        uint32_t bh0, bh1, bh2, bh3;
                        ldsm4(bh0, bh1, bh2, bh3, aH);
                        mma16816(s[np * 2],     qh[ks][0], qh[ks][1], qh[ks][2], qh[ks][3], bh0, bh1);
                        mma16816(s[np * 2 + 1], qh[ks][0], qh[ks][1], qh[ks][2], qh[ks][3], bh2, bh3);
                    }
                }

                if (myt == qt) {
                    const int r0 = wq4 * 16 + g;
                    const int r1 = r0 + 8;
                    #pragma unroll
                    for (int nb = 0; nb < 8; ++nb) {
                        int c0 = nb * 8 + tg * 2;
                        if (c0     > r0) s[nb][0] = -INFINITY;
                        if (c0 + 1 > r0) s[nb][1] = -INFINITY;
                        if (c0     > r1) s[nb][2] = -INFINITY;
                        if (c0 + 1 > r1) s[nb][3] = -INFINITY;
                    }
                }

                float rm0 = -INFINITY, rm1 = -INFINITY;
                #pragma unroll
                for (int nb = 0; nb < 8; ++nb) {
                    rm0 = fmaxf(rm0, fmaxf(s[nb][0], s[nb][1]));
                    rm1 = fmaxf(rm1, fmaxf(s[nb][2], s[nb][3]));
                }
                rm0 = fmaxf(rm0, __shfl_xor_sync(0xffffffffu, rm0, 1));
                rm0 = fmaxf(rm0, __shfl_xor_sync(0xffffffffu, rm0, 2));
                rm1 = fmaxf(rm1, __shfl_xor_sync(0xffffffffu, rm1, 1));
                rm1 = fmaxf(rm1, __shfl_xor_sync(0xffffffffu, rm1, 2));
                float mn0 = fmaxf(m0, rm0), mn1 = fmaxf(m1, rm1);
                float al0 = __expf(m0 - mn0), al1 = __expf(m1 - mn1);
                float rs0 = 0.f, rs1 = 0.f;
                #pragma unroll
                for (int nb = 0; nb < 8; ++nb) {
                    s[nb][0] = __expf(s[nb][0] - mn0);
                    s[nb][1] = __expf(s[nb][1] - mn0);
                    s[nb][2] = __expf(s[nb][2] - mn1);
                    s[nb][3] = __expf(s[nb][3] - mn1);
                    rs0 += s[nb][0] + s[nb][1];
                    rs1 += s[nb][2] + s[nb][3];
                }
                rs0 += __shfl_xor_sync(0xffffffffu, rs0, 1);
                rs0 += __shfl_xor_sync(0xffffffffu, rs0, 2);
                rs1 += __shfl_xor_sync(0xffffffffu, rs1, 1);
                rs1 += __shfl_xor_sync(0xffffffffu, rs1, 2);
                l0 = l0 * al0 + rs0; m0 = mn0;
                l1 = l1 * al1 + rs1; m1 = mn1;
                #pragma unroll
                for (int nb = 0; nb < 8; ++nb) {
                    o[nb][0] *= al0; o[nb][1] *= al0;
                    o[nb][2] *= al1; o[nb][3] *= al1;
                }

                #pragma unroll
                for (int ks = 0; ks < 4; ++ks) {
                    float p00 = s[2 * ks][0],     p01 = s[2 * ks][1];
                    float p02 = s[2 * ks][2],     p03 = s[2 * ks][3];
                    float p10 = s[2 * ks + 1][0], p11 = s[2 * ks + 1][1];
                    float p12 = s[2 * ks + 1][2], p13 = s[2 * ks + 1][3];
                    uint32_t pah0 = pk2(p00, p01), pah1 = pk2(p02, p03);
                    uint32_t pah2 = pk2(p10, p11), pah3 = pk2(p12, p13);
                    uint32_t pal0 = pk2(p00 - bfround(p00), p01 - bfround(p01));
                    uint32_t pal1 = pk2(p02 - bfround(p02), p03 - bfround(p03));
                    uint32_t pal2 = pk2(p10 - bfround(p10), p11 - bfround(p11));
                    uint32_t pal3 = pk2(p12 - bfround(p12), p13 - bfround(p13));
                    #pragma unroll
                    for (int hp = 0; hp < 4; ++hp) {
                        uint32_t aV = kv_s + (ks * 16 + v_row) * KVROW + v_col + hp * 32;
                        uint32_t vh0, vh1, vh2, vh3, vl0, vl1, vl2, vl3;
                        ldsm4t(vh0, vh1, vh2, vh3, aV);
                        ldsm4t(vl0, vl1, vl2, vl3, aV + ARR_B);
                        mma16816(o[hp * 2],     pah0, pah1, pah2, pah3, vh0, vh1);
                        mma16816(o[hp * 2],     pah0, pah1, pah2, pah3, vl0, vl1);
                        mma16816(o[hp * 2],     pal0, pal1, pal2, pal3, vh0, vh1);
                        mma16816(o[hp * 2 + 1], pah0, pah1, pah2, pah3, vh2, vh3);
                        mma16816(o[hp * 2 + 1], pah0, pah1, pah2, pah3, vl2, vl3);
                        mma16816(o[hp * 2 + 1], pal0, pal1, pal2, pal3, vh2, vh3);
                    }
                }
            }
            __syncthreads();
            issue_tile(2 * it + 4);
            issue_tile(2 * it + 5);
        }

        if (wgrp == 1) {
            float* p = msm + ((size_t)(wq4 * 32 + lane)) * 36;
            #pragma unroll
            for (int nb = 0; nb < 8; ++nb) {
                p[nb * 4 + 0] = o[nb][0]; p[nb * 4 + 1] = o[nb][1];
                p[nb * 4 + 2] = o[nb][2]; p[nb * 4 + 3] = o[nb][3];
            }
            p[32] = m0; p[33] = l0; p[34] = m1; p[35] = l1;
        }
        __syncthreads();
        if (wgrp == 0) {
            const float* p = msm + ((size_t)(wq4 * 32 + lane)) * 36;
            float om0 = p[32], ol0 = p[33], om1 = p[34], ol1 = p[35];
            float M0 = fmaxf(m0, om0), M1 = fmaxf(m1, om1);
            float A0 = __expf(m0 - M0), B0 = __expf(om0 - M0);
            float A1 = __expf(m1 - M1), B1 = __expf(om1 - M1);
            float inv0 = 1.0f / (l0 * A0 + ol0 * B0);
            float inv1 = 1.0f / (l1 * A1 + ol1 * B1);
            float* orow0 = out + (size_t)(bt0 + q0 + wq4 * 16 + g) * H_;
            float* orow1 = orow0 + 8 * H_;
            #pragma unroll
            for (int nb = 0; nb < 8; ++nb) {
                int col = nb * 8 + tg * 2;
                float e0 = (o[nb][0] * A0 + p[nb * 4 + 0] * B0) * inv0;
                float e1 = (o[nb][1] * A0 + p[nb * 4 + 1] * B0) * inv0;
                float e2 = (o[nb][2] * A1 + p[nb * 4 + 2] * B1) * inv1;
                float e3 = (o[nb][3] * A1 + p[nb * 4 + 3] * B1) * inv1;
                *(float2*)(orow0 + col) = make_float2(e0, e1);
                *(float2*)(orow1 + col) = make_float2(e2, e3);
            }
        }
    }
}

// ---------------------------------------------------------------------------
extern "C" void kernel_launch(void* const* d_in, const int* in_sizes, int n_in,
                              void* d_out, int out_size)
{
    const float* x  = (const float*)d_in[0];
    const float* wq = (const float*)d_in[1];
    const float* bq = (const float*)d_in[2];
    const float* wk = (const float*)d_in[3];
    const float* bk = (const float*)d_in[4];
    const float* wv = (const float*)d_in[5];
    const float* bv = (const float*)d_in[6];
    float* out = (float*)d_out;

    prep_w<<<(3 * H_ * C_ + 255) / 256, 256>>>(wq, wk, wv);

    cudaFuncSetAttribute(proj_mma, cudaFuncAttributeMaxDynamicSharedMemorySize, PROJ_SMEM);
    proj_mma<<<128, 256, PROJ_SMEM>>>(x, bq, bk, bv);

    cudaFuncSetAttribute(attn_mma, cudaFuncAttributeMaxDynamicSharedMemorySize, ATTN_SMEM);
    attn_mma<<<dim3(16, 8), 256, ATTN_SMEM>>>(out);
}

// round 15
// speedup vs baseline: 1.0220x; 1.0004x over previous
#include <cuda_runtime.h>
#include <cuda_bf16.h>
#include <math.h>
#include <stdint.h>

// Problem constants
#define B_   8
#define T_   2048
#define C_   1024
#define H_   64
#define NROW (B_ * T_)          // 16384

// Scratch: Q (pre-scaled 1/32) and K as single bf16; V as bf16 hi/lo.
__device__ __nv_bfloat16 g_Qh[NROW * H_];
__device__ __nv_bfloat16 g_Kh[NROW * H_];
__device__ __nv_bfloat16 g_Vh[NROW * H_], g_Vl[NROW * H_];
__device__ __nv_bfloat16 g_Wh[3 * H_ * C_];
__device__ __nv_bfloat16 g_Wl[3 * H_ * C_];

__device__ __forceinline__ uint32_t smem_u32(const void* p) {
    uint32_t a;
    asm("{ .reg .u64 t; cvta.to.shared.u64 t, %1; cvt.u32.u64 %0, t; }" : "=r"(a) : "l"(p));
    return a;
}
__device__ __forceinline__ void ldsm4(uint32_t& r0, uint32_t& r1, uint32_t& r2,
                                      uint32_t& r3, uint32_t addr) {
    asm volatile("ldmatrix.sync.aligned.m8n8.x4.shared.b16 {%0,%1,%2,%3}, [%4];"
                 : "=r"(r0), "=r"(r1), "=r"(r2), "=r"(r3) : "r"(addr));
}
__device__ __forceinline__ void ldsm4t(uint32_t& r0, uint32_t& r1, uint32_t& r2,
                                       uint32_t& r3, uint32_t addr) {
    asm volatile("ldmatrix.sync.aligned.m8n8.x4.trans.shared.b16 {%0,%1,%2,%3}, [%4];"
                 : "=r"(r0), "=r"(r1), "=r"(r2), "=r"(r3) : "r"(addr));
}
__device__ __forceinline__ void mma16816(float* d, uint32_t a0, uint32_t a1,
                                         uint32_t a2, uint32_t a3,
                                         uint32_t b0, uint32_t b1) {
    asm volatile("mma.sync.aligned.m16n8k16.row.col.f32.bf16.bf16.f32 "
                 "{%0,%1,%2,%3}, {%4,%5,%6,%7}, {%8,%9}, {%0,%1,%2,%3};"
                 : "+f"(d[0]), "+f"(d[1]), "+f"(d[2]), "+f"(d[3])
                 : "r"(a0), "r"(a1), "r"(a2), "r"(a3), "r"(b0), "r"(b1));
}
__device__ __forceinline__ uint32_t pk2(float lo, float hi) {
    uint32_t r;
    asm("cvt.rn.bf16x2.f32 %0, %1, %2;" : "=r"(r) : "f"(hi), "f"(lo));
    return r;
}
__device__ __forceinline__ float bfround(float v) {
    return __bfloat162float(__float2bfloat16(v));
}
__device__ __forceinline__ uint32_t pack_bf16(__nv_bfloat16 a, __nv_bfloat16 b) {
    __nv_bfloat162 t; t.x = a; t.y = b;
    return *(uint32_t*)&t;
}
#define CP16(dst, src) \
    asm volatile("cp.async.cg.shared.global [%0], [%1], 16;" :: "r"(dst), "l"(src) : "memory")
#define CP_COMMIT() asm volatile("cp.async.commit_group;" ::: "memory")

// ---------------------------------------------------------------------------
// Prep: split weights fp32 -> bf16 hi/lo, transpose [k][n] -> [mat][n][k]
// ---------------------------------------------------------------------------
__global__ void prep_w(const float* __restrict__ wq,
                       const float* __restrict__ wk,
                       const float* __restrict__ wv)
{
    int e = blockIdx.x * 256 + threadIdx.x;
    if (e >= 3 * H_ * C_) return;
    int mat = e / (H_ * C_);
    int r   = e % (H_ * C_);
    int n   = r / C_;
    int k   = r % C_;
    const float* w = (mat == 0) ? wq : (mat == 1) ? wk : wv;
    float v = w[k * H_ + n];
    __nv_bfloat16 h = __float2bfloat16(v);
    g_Wh[e] = h;
    g_Wl[e] = __float2bfloat16(v - __bfloat162float(h));
}

// ---------------------------------------------------------------------------
// Projection via mma.sync, software-pipelined.
//   Q/K: single-bf16 MMA (xh.wh). V: 3-way hi/lo split (accuracy-critical).
//   W: cp.async double buffer (Wl staged for V only); x: reg prefetch ->
//   single-buffered bf16 hi/lo smem. grid = 128 CTAs x 256 threads.
// ---------------------------------------------------------------------------
#define KP 72
#define XBUF_B 36864                           // xh(18432) + xl(18432)
#define WBUF_B 36864                           // Wh 3 mats (27648) + Wl V (9216)
#define WB(b)  (XBUF_B + (b) * WBUF_B)
#define PROJ_SMEM (XBUF_B + 2 * WBUF_B)        // 110592

__global__ __launch_bounds__(256) void proj_mma(
    const float* __restrict__ x,
    const float* __restrict__ bq,
    const float* __restrict__ bk,
    const float* __restrict__ bv)
{
    extern __shared__ char smc[];
    const uint32_t sb = smem_u32(smc);
    const int tid  = threadIdx.x;
    const int wid  = tid >> 5;
    const int lane = tid & 31;
    const int m0   = blockIdx.x * 128;

    float acc[3][8][4];
    #pragma unroll
    for (int m = 0; m < 3; ++m)
        #pragma unroll
        for (int n = 0; n < 8; ++n)
            #pragma unroll
            for (int i = 0; i < 4; ++i) acc[m][n][i] = 0.f;

    const int a_row  = lane & 15;
    const int a_half = lane >> 4;
    const uint32_t a_off = ((wid * 16 + a_row) * KP + a_half * 8) * 2;
    const int l8   = lane & 7;
    const int bgrp = lane >> 3;
    const int b_n  = ((bgrp & 2) ? 8 : 0) + l8;
    const int b_h  = bgrp & 1;
    const uint32_t b_off = (b_n * KP + b_h * 8) * 2;

    float4 X[8];
    auto ldg_x = [&](int kc) {
        #pragma unroll
        for (int it = 0; it < 8; ++it) {
            int u  = tid + it * 256;
            int r  = u >> 4;
            int c4 = (u & 15) << 2;
            X[it] = *(const float4*)(x + (size_t)(m0 + r) * C_ + kc + c4);
        }
    };
    auto cvt_x = [&]() {
        #pragma unroll
        for (int it = 0; it < 8; ++it) {
            int u  = tid + it * 256;
            int r  = u >> 4;
            int c4 = (u & 15) << 2;
            float4 t = X[it];
            __nv_bfloat16 h0 = __float2bfloat16(t.x);
            __nv_bfloat16 h1 = __float2bfloat16(t.y);
            __nv_bfloat16 h2 = __float2bfloat16(t.z);
            __nv_bfloat16 h3 = __float2bfloat16(t.w);
            uint2 hh = make_uint2(pack_bf16(h0, h1), pack_bf16(h2, h3));
            uint2 ll = make_uint2(
                pack_bf16(__float2bfloat16(t.x - __bfloat162float(h0)),
                          __float2bfloat16(t.y - __bfloat162float(h1))),
                pack_bf16(__float2bfloat16(t.z - __bfloat162float(h2)),
                          __float2bfloat16(t.w - __bfloat162float(h3))));
            int off = (r * KP + c4) * 2;
            *(uint2*)(smc + off)         = hh;
            *(uint2*)(smc + 18432 + off) = ll;
        }
    };
    auto cpw = [&](int kc, int buf) {
        // Wh for all 3 mats (192 rows)
        #pragma unroll
        for (int j = 0; j < 6; ++j) {
            int rem = tid + j * 256;              // 0..1535
            int nab = rem >> 3;                   // 0..191 = mat*64+n
            int c8  = rem & 7;
            CP16(sb + WB(buf) + nab * 144 + c8 * 16,
                 g_Wh + (size_t)nab * C_ + kc + c8 * 8);
        }
        // Wl for V only (64 rows)
        #pragma unroll
        for (int j = 0; j < 2; ++j) {
            int rem = tid + j * 256;              // 0..511
            int n   = rem >> 3;                   // 0..63
            int c8  = rem & 7;
            CP16(sb + WB(buf) + 27648 + n * 144 + c8 * 16,
                 g_Wl + (size_t)(2 * H_ * C_) + (size_t)n * C_ + kc + c8 * 8);
        }
        CP_COMMIT();
    };

    ldg_x(0);
    cpw(0, 0);

    #pragma unroll 1
    for (int c = 0; c < 16; ++c) {
        const int wbuf = c & 1;
        if (c < 15) cpw((c + 1) * 64, wbuf ^ 1);
        cvt_x();
        if (c < 15) ldg_x((c + 1) * 64);
        if (c < 15) asm volatile("cp.async.wait_group 1;" ::: "memory");
        else        asm volatile("cp.async.wait_group 0;" ::: "memory");
        __syncthreads();

        const uint32_t xa = sb + a_off;
        #pragma unroll
        for (int ks = 0; ks < 4; ++ks) {
            uint32_t ah0, ah1, ah2, ah3, al0, al1, al2, al3;
            ldsm4(ah0, ah1, ah2, ah3, xa + ks * 32);
            ldsm4(al0, al1, al2, al3, xa + 18432 + ks * 32);
            // Q, K: single-bf16
            #pragma unroll
            for (int mat = 0; mat < 2; ++mat) {
                #pragma unroll
                for (int nb2 = 0; nb2 < 4; ++nb2) {
                    uint32_t wa = sb + WB(wbuf) + (mat * 64 + nb2 * 16) * 144
                                + ks * 32 + b_off;
                    uint32_t bh0, bh1, bh2, bh3;
                    ldsm4(bh0, bh1, bh2, bh3, wa);
                    mma16816(acc[mat][nb2 * 2],     ah0, ah1, ah2, ah3, bh0, bh1);
                    mma16816(acc[mat][nb2 * 2 + 1], ah0, ah1, ah2, ah3, bh2, bh3);
                }
            }
            // V: full hi/lo split
            #pragma unroll
            for (int nb2 = 0; nb2 < 4; ++nb2) {
                uint32_t wa = sb + WB(wbuf) + (2 * 64 + nb2 * 16) * 144
                            + ks * 32 + b_off;
                uint32_t wl = sb + WB(wbuf) + 27648 + (nb2 * 16) * 144
                            + ks * 32 + b_off;
                uint32_t bh0, bh1, bh2, bh3, bl0, bl1, bl2, bl3;
                ldsm4(bh0, bh1, bh2, bh3, wa);
                ldsm4(bl0, bl1, bl2, bl3, wl);
                mma16816(acc[2][nb2 * 2],     ah0, ah1, ah2, ah3, bh0, bh1);
                mma16816(acc[2][nb2 * 2],     ah0, ah1, ah2, ah3, bl0, bl1);
                mma16816(acc[2][nb2 * 2],     al0, al1, al2, al3, bh0, bh1);
                mma16816(acc[2][nb2 * 2 + 1], ah0, ah1, ah2, ah3, bh2, bh3);
                mma16816(acc[2][nb2 * 2 + 1], ah0, ah1, ah2, ah3, bl2, bl3);
                mma16816(acc[2][nb2 * 2 + 1], al0, al1, al2, al3, bh2, bh3);
            }
        }
        __syncthreads();
    }

    // --- epilogue: Q (scaled 1/32) and K single bf16; V hi/lo ---
    const int g  = lane >> 2;
    const int tg = lane & 3;
    const int row = m0 + wid * 16 + g;
    #pragma unroll
    for (int mat = 0; mat < 3; ++mat) {
        const float* bias = (mat == 0) ? bq : (mat == 1) ? bk : bv;
        __nv_bfloat16* dh = (mat == 0) ? g_Qh : (mat == 1) ? g_Kh : g_Vh;
        const float scl = (mat == 0) ? 0.03125f : 1.0f;
        #pragma unroll
        for (int nb = 0; nb < 8; ++nb) {
            int col = nb * 8 + tg * 2;
            float b0 = __ldg(bias + col);
            float b1 = __ldg(bias + col + 1);
            float v0 = (acc[mat][nb][0] + b0) * scl;
            float v1 = (acc[mat][nb][1] + b1) * scl;
            float v2 = (acc[mat][nb][2] + b0) * scl;
            float v3 = (acc[mat][nb][3] + b1) * scl;
            __nv_bfloat16 h0 = __float2bfloat16(v0), h1 = __float2bfloat16(v1);
            __nv_bfloat16 h2 = __float2bfloat16(v2), h3 = __float2bfloat16(v3);
            size_t o0 = (size_t)row * H_ + col;
            size_t o1 = (size_t)(row + 8) * H_ + col;
            *(uint32_t*)(dh + o0) = pack_bf16(h0, h1);
            *(uint32_t*)(dh + o1) = pack_bf16(h2, h3);
            if (mat == 2) {
                *(uint32_t*)(g_Vl + o0) = pack_bf16(
                    __float2bfloat16(v0 - __bfloat162float(h0)),
                    __float2bfloat16(v1 - __bfloat162float(h1)));
                *(uint32_t*)(g_Vl + o1) = pack_bf16(
                    __float2bfloat16(v2 - __bfloat162float(h2)),
                    __float2bfloat16(v3 - __bfloat162float(h3)));
            }
        }
    }
}

// ---------------------------------------------------------------------------
// HMMA flash attention (unchanged from verified R7): 8 warps, even/odd
// k-tile split, single-bf16 S, hi/lo-split PV, 4-deep cp.async ring.
// ---------------------------------------------------------------------------
#define KVROW 144
#define ARR_B (64 * KVROW)        // 9216
#define TILE_B (3 * ARR_B)        // 27648: Kh,Vh,Vl
#define ATTN_SMEM (4 * TILE_B)    // 110592

__global__ __launch_bounds__(256) void attn_mma(float* __restrict__ out)
{
    extern __shared__ __align__(16) char smk[];
    const uint32_t sb = smem_u32(smk);
    float* msm = (float*)smk;
    const int tid  = threadIdx.x;
    const int lane = tid & 31;
    const int wid  = tid >> 5;
    const int wgrp = wid >> 2;
    const int wq4  = wid & 3;
    const int b    = blockIdx.y;
    const int px   = blockIdx.x;
    const int g    = lane >> 2;
    const int tg   = lane & 3;
    const int l8   = lane & 7;
    const int bgrp = lane >> 3;
    const int k_row = ((bgrp & 2) ? 8 : 0) + l8;
    const int k_col = (bgrp & 1) * 16;
    const int v_row = ((bgrp & 1) ? 8 : 0) + l8;
    const int v_col = (bgrp & 2) ? 16 : 0;
    const int bt0   = b * T_;

    #pragma unroll 1
    for (int half = 0; half < 2; ++half) {
        const int qt = half ? (31 - px) : px;
        const int q0 = qt * 64;
        const int nk = qt + 1;

        __syncthreads();

        uint32_t qh[4][4];
        {
            const uint32_t* qhp = (const uint32_t*)g_Qh + (size_t)(bt0 + q0 + wq4 * 16) * 32;
            #pragma unroll
            for (int ks = 0; ks < 4; ++ks) {
                int i0 = g * 32 + ks * 8 + tg;
                int i1 = (g + 8) * 32 + ks * 8 + tg;
                qh[ks][0] = qhp[i0];     qh[ks][1] = qhp[i1];
                qh[ks][2] = qhp[i0 + 4]; qh[ks][3] = qhp[i1 + 4];
            }
        }

        float m0 = -INFINITY, m1 = -INFINITY, l0 = 0.f, l1 = 0.f;
        float o[8][4];
        #pragma unroll
        for (int nb = 0; nb < 8; ++nb)
            o[nb][0] = o[nb][1] = o[nb][2] = o[nb][3] = 0.f;

        auto issue_tile = [&](int vt) {
            if (vt < nk) {
                uint32_t db = sb + (vt & 3) * TILE_B;
                size_t r0 = (size_t)(bt0 + vt * 64);
                #pragma unroll
                for (int j = 0; j < 6; ++j) {
                    int rem = tid + j * 256;
                    int arr = rem >> 9;
                    int idx = rem & 511;
                    int row = idx >> 3;
                    int c8  = idx & 7;
                    const __nv_bfloat16* sp = (arr == 0) ? g_Kh : (arr == 1) ? g_Vh : g_Vl;
                    CP16(db + arr * ARR_B + row * KVROW + c8 * 16,
                         sp + (r0 + row) * 64 + c8 * 8);
                }
            }
            CP_COMMIT();
        };

        issue_tile(0); issue_tile(1); issue_tile(2); issue_tile(3);

        const int iters = (nk + 1) >> 1;
        #pragma unroll 1
        for (int it = 0; it < iters; ++it) {
            asm volatile("cp.async.wait_group 2;" ::: "memory");
            __syncthreads();

            const int myt = 2 * it + wgrp;
            if (myt < nk) {
                const uint32_t kb_s = sb + (myt & 3) * TILE_B;
                const uint32_t kv_s = kb_s + ARR_B;

                float s[8][4];
                #pragma unroll
                for (int nb = 0; nb < 8; ++nb)
                    s[nb][0] = s[nb][1] = s[nb][2] = s[nb][3] = 0.f;

                #pragma unroll
                for (int ks = 0; ks < 4; ++ks) {
                    #pragma unroll
                    for (int np = 0; np < 4; ++np) {
                        uint32_t aH = kb_s + (np * 16 + k_row) * KVROW + k_col + ks * 32;
                        uint32_t bh0, bh1, bh2, bh3;
                        ldsm4(bh0, bh1, bh2, bh3, aH);
                        mma16816(s[np * 2],     qh[ks][0], qh[ks][1], qh[ks][2], qh[ks][3], bh0, bh1);
                        mma16816(s[np * 2 + 1], qh[ks][0], qh[ks][1], qh[ks][2], qh[ks][3], bh2, bh3);
                    }
                }

                if (myt == qt) {
                    const int r0 = wq4 * 16 + g;
                    const int r1 = r0 + 8;
                    #pragma unroll
                    for (int nb = 0; nb < 8; ++nb) {
                        int c0 = nb * 8 + tg * 2;
                        if (c0     > r0) s[nb][0] = -INFINITY;
                        if (c0 + 1 > r0) s[nb][1] = -INFINITY;
                        if (c0     > r1) s[nb][2] = -INFINITY;
                        if (c0 + 1 > r1) s[nb][3] = -INFINITY;
                    }
                }

                float rm0 = -INFINITY, rm1 = -INFINITY;
                #pragma unroll
                for (int nb = 0; nb < 8; ++nb) {
                    rm0 = fmaxf(rm0, fmaxf(s[nb][0], s[nb][1]));
                    rm1 = fmaxf(rm1, fmaxf(s[nb][2], s[nb][3]));
                }
                rm0 = fmaxf(rm0, __shfl_xor_sync(0xffffffffu, rm0, 1));
                rm0 = fmaxf(rm0, __shfl_xor_sync(0xffffffffu, rm0, 2));
                rm1 = fmaxf(rm1, __shfl_xor_sync(0xffffffffu, rm1, 1));
                rm1 = fmaxf(rm1, __shfl_xor_sync(0xffffffffu, rm1, 2));
                float mn0 = fmaxf(m0, rm0), mn1 = fmaxf(m1, rm1);
                float al0 = __expf(m0 - mn0), al1 = __expf(m1 - mn1);
                float rs0 = 0.f, rs1 = 0.f;
                #pragma unroll
                for (int nb = 0; nb < 8; ++nb) {
                    s[nb][0] = __expf(s[nb][0] - mn0);
                    s[nb][1] = __expf(s[nb][1] - mn0);
                    s[nb][2] = __expf(s[nb][2] - mn1);
                    s[nb][3] = __expf(s[nb][3] - mn1);
                    rs0 += s[nb][0] + s[nb][1];
                    rs1 += s[nb][2] + s[nb][3];
                }
                rs0 += __shfl_xor_sync(0xffffffffu, rs0, 1);
                rs0 += __shfl_xor_sync(0xffffffffu, rs0, 2);
                rs1 += __shfl_xor_sync(0xffffffffu, rs1, 1);
                rs1 += __shfl_xor_sync(0xffffffffu, rs1, 2);
                l0 = l0 * al0 + rs0; m0 = mn0;
                l1 = l1 * al1 + rs1; m1 = mn1;
                #pragma unroll
                for (int nb = 0; nb < 8; ++nb) {
                    o[nb][0] *= al0; o[nb][1] *= al0;
                    o[nb][2] *= al1; o[nb][3] *= al1;
                }

                #pragma unroll
                for (int ks = 0; ks < 4; ++ks) {
                    float p00 = s[2 * ks][0],     p01 = s[2 * ks][1];
                    float p02 = s[2 * ks][2],     p03 = s[2 * ks][3];
                    float p10 = s[2 * ks + 1][0], p11 = s[2 * ks + 1][1];
                    float p12 = s[2 * ks + 1][2], p13 = s[2 * ks + 1][3];
                    uint32_t pah0 = pk2(p00, p01), pah1 = pk2(p02, p03);
                    uint32_t pah2 = pk2(p10, p11), pah3 = pk2(p12, p13);
                    uint32_t pal0 = pk2(p00 - bfround(p00), p01 - bfround(p01));
                    uint32_t pal1 = pk2(p02 - bfround(p02), p03 - bfround(p03));
                    uint32_t pal2 = pk2(p10 - bfround(p10), p11 - bfround(p11));
                    uint32_t pal3 = pk2(p12 - bfround(p12), p13 - bfround(p13));
                    #pragma unroll
                    for (int hp = 0; hp < 4; ++hp) {
                        uint32_t aV = kv_s + (ks * 16 + v_row) * KVROW + v_col + hp * 32;
                        uint32_t vh0, vh1, vh2, vh3, vl0, vl1, vl2, vl3;
                        ldsm4t(vh0, vh1, vh2, vh3, aV);
                        ldsm4t(vl0, vl1, vl2, vl3, aV + ARR_B);
                        mma16816(o[hp * 2],     pah0, pah1, pah2, pah3, vh0, vh1);
                        mma16816(o[hp * 2],     pah0, pah1, pah2, pah3, vl0, vl1);
                        mma16816(o[hp * 2],     pal0, pal1, pal2, pal3, vh0, vh1);
                        mma16816(o[hp * 2 + 1], pah0, pah1, pah2, pah3, vh2, vh3);
                        mma16816(o[hp * 2 + 1], pah0, pah1, pah2, pah3, vl2, vl3);
                        mma16816(o[hp * 2 + 1], pal0, pal1, pal2, pal3, vh2, vh3);
                    }
                }
            }
            __syncthreads();
            issue_tile(2 * it + 4);
            issue_tile(2 * it + 5);
        }

        if (wgrp == 1) {
            float* p = msm + ((size_t)(wq4 * 32 + lane)) * 36;
            #pragma unroll
            for (int nb = 0; nb < 8; ++nb) {
                p[nb * 4 + 0] = o[nb][0]; p[nb * 4 + 1] = o[nb][1];
                p[nb * 4 + 2] = o[nb][2]; p[nb * 4 + 3] = o[nb][3];
            }
            p[32] = m0; p[33] = l0; p[34] = m1; p[35] = l1;
        }
        __syncthreads();
        if (wgrp == 0) {
            const float* p = msm + ((size_t)(wq4 * 32 + lane)) * 36;
            float om0 = p[32], ol0 = p[33], om1 = p[34], ol1 = p[35];
            float M0 = fmaxf(m0, om0), M1 = fmaxf(m1, om1);
            float A0 = __expf(m0 - M0), B0 = __expf(om0 - M0);
            float A1 = __expf(m1 - M1), B1 = __expf(om1 - M1);
            float inv0 = 1.0f / (l0 * A0 + ol0 * B0);
            float inv1 = 1.0f / (l1 * A1 + ol1 * B1);
            float* orow0 = out + (size_t)(bt0 + q0 + wq4 * 16 + g) * H_;
            float* orow1 = orow0 + 8 * H_;
            #pragma unroll
            for (int nb = 0; nb < 8; ++nb) {
                int col = nb * 8 + tg * 2;
                float e0 = (o[nb][0] * A0 + p[nb * 4 + 0] * B0) * inv0;
                float e1 = (o[nb][1] * A0 + p[nb * 4 + 1] * B0) * inv0;
                float e2 = (o[nb][2] * A1 + p[nb * 4 + 2] * B1) * inv1;
                float e3 = (o[nb][3] * A1 + p[nb * 4 + 3] * B1) * inv1;
                *(float2*)(orow0 + col) = make_float2(e0, e1);
                *(float2*)(orow1 + col) = make_float2(e2, e3);
            }
        }
    }
}

// ---------------------------------------------------------------------------
extern "C" void kernel_launch(void* const* d_in, const int* in_sizes, int n_in,
                              void* d_out, int out_size)
{
    const float* x  = (const float*)d_in[0];
    const float* wq = (const float*)d_in[1];
    const float* bq = (const float*)d_in[2];
    const float* wk = (const float*)d_in[3];
    const float* bk = (const float*)d_in[4];
    const float* wv = (const float*)d_in[5];
    const float* bv = (const float*)d_in[6];
    float* out = (float*)d_out;

    prep_w<<<(3 * H_ * C_ + 255) / 256, 256>>>(wq, wk, wv);

    cudaFuncSetAttribute(proj_mma, cudaFuncAttributeMaxDynamicSharedMemorySize, PROJ_SMEM);
    proj_mma<<<128, 256, PROJ_SMEM>>>(x, bq, bk, bv);

    cudaFuncSetAttribute(attn_mma, cudaFuncAttributeMaxDynamicSharedMemorySize, ATTN_SMEM);
    attn_mma<<<dim3(16, 8), 256, ATTN_SMEM>>>(out);
}